// round 11
// baseline (speedup 1.0000x reference)
#include <cuda_runtime.h>
#include <cuda_bf16.h>
#include <cstdint>
#include <cstddef>

#define NMAX 100000
#define EMAX 600000
#define FMAX 200000
#define C    128

// ---------------- scratch (static device globals; no runtime alloc) ----------
__device__ float g_x[(size_t)NMAX * C];      // features @ Wlin + blin
__device__ float g_p[(size_t)NMAX * C];      // aggregated & den-normalized rows
__device__ float g_nacc[NMAX * 3];           // accumulated face normals (raw)
__device__ float g_stats[256];               // colsum[128], colsum2[128]
// CSR-by-dst
__device__ int   g_deg[NMAX];
__device__ int   g_scan[NMAX];               // in-block exclusive scan
__device__ int   g_part[128];                // block partial sums
__device__ int   g_partscan[128];
__device__ int   g_start[NMAX + 1];
__device__ int   g_cursor[NMAX];
__device__ int   g_csr_src[EMAX];
__device__ float g_csr_w[EMAX];
// pre-converted W as bf16 hi/lo pairs, layout [n][k-pair] with pitch 68 u32
#define BPITCH 68
__device__ uint32_t g_Bh[128 * BPITCH];
__device__ uint32_t g_Bl[128 * BPITCH];

// ---------------- W pre-convert: fp32 -> bf16 hi/lo [n][k] pitch-68 ----------
__global__ void k_prepB(const float* __restrict__ W, uint32_t* __restrict__ bh,
                        uint32_t* __restrict__ bl) {
    int idx = blockIdx.x * blockDim.x + threadIdx.x;   // 128 cols * 64 k-pairs
    if (idx >= 128 * 64) return;
    int c = idx >> 6, kp = idx & 63;
    float v0 = __ldg(W + (size_t)(2 * kp) * C + c);
    float v1 = __ldg(W + (size_t)(2 * kp + 1) * C + c);
    __nv_bfloat16 h0 = __float2bfloat16_rn(v0);
    __nv_bfloat16 h1 = __float2bfloat16_rn(v1);
    __nv_bfloat16 l0 = __float2bfloat16_rn(v0 - __bfloat162float(h0));
    __nv_bfloat16 l1 = __float2bfloat16_rn(v1 - __bfloat162float(h1));
    __nv_bfloat162 H(h0, h1), L(l0, l1);
    bh[c * BPITCH + kp] = *(uint32_t*)&H;
    bl[c * BPITCH + kp] = *(uint32_t*)&L;
}

// ---------------- zero helper ------------------------------------------------
__global__ void k_zero_misc(float* __restrict__ nacc, int* __restrict__ deg,
                            float* __restrict__ stats, int n) {
    int i = blockIdx.x * blockDim.x + threadIdx.x;
    if (i < n * 3) nacc[i] = 0.0f;
    if (i < n) deg[i] = 0;
    if (i < 256) stats[i] = 0.0f;
}

// ---------------- face normals (scatter) + dst degree count ------------------
__global__ void k_face_count(const int* __restrict__ faces, const float* __restrict__ verts,
                             const int* __restrict__ edges, float* __restrict__ nacc,
                             int* __restrict__ deg, int F, int E) {
    int t = blockIdx.x * blockDim.x + threadIdx.x;
    if (t < F) {
        int f = t;
        int i0 = __ldg(faces + f);
        int i1 = __ldg(faces + F + f);
        int i2 = __ldg(faces + 2 * F + f);
        float v0x = __ldg(verts + 3 * i0), v0y = __ldg(verts + 3 * i0 + 1), v0z = __ldg(verts + 3 * i0 + 2);
        float v1x = __ldg(verts + 3 * i1), v1y = __ldg(verts + 3 * i1 + 1), v1z = __ldg(verts + 3 * i1 + 2);
        float v2x = __ldg(verts + 3 * i2), v2y = __ldg(verts + 3 * i2 + 1), v2z = __ldg(verts + 3 * i2 + 2);
        float ax = v1x - v0x, ay = v1y - v0y, az = v1z - v0z;
        float bx = v2x - v0x, by = v2y - v0y, bz = v2z - v0z;
        float nx = ay * bz - az * by;
        float ny = az * bx - ax * bz;
        float nz = ax * by - ay * bx;
        atomicAdd(&nacc[3 * i0 + 0], nx); atomicAdd(&nacc[3 * i0 + 1], ny); atomicAdd(&nacc[3 * i0 + 2], nz);
        atomicAdd(&nacc[3 * i1 + 0], nx); atomicAdd(&nacc[3 * i1 + 1], ny); atomicAdd(&nacc[3 * i1 + 2], nz);
        atomicAdd(&nacc[3 * i2 + 0], nx); atomicAdd(&nacc[3 * i2 + 1], ny); atomicAdd(&nacc[3 * i2 + 2], nz);
    } else {
        int e = t - F;
        if (e < E) atomicAdd(&deg[__ldg(edges + E + e)], 1);
    }
}

// ---------------- mma.sync helpers -------------------------------------------
__device__ __forceinline__ void mma16816(float* c, const uint32_t* a,
                                         uint32_t b0, uint32_t b1) {
    asm volatile(
        "mma.sync.aligned.m16n8k16.row.col.f32.bf16.bf16.f32 "
        "{%0,%1,%2,%3}, {%4,%5,%6,%7}, {%8,%9}, {%0,%1,%2,%3};"
        : "+f"(c[0]), "+f"(c[1]), "+f"(c[2]), "+f"(c[3])
        : "r"(a[0]), "r"(a[1]), "r"(a[2]), "r"(a[3]), "r"(b0), "r"(b1));
}

__device__ __forceinline__ void cvt2(float2 v, uint32_t& hi, uint32_t& lo) {
    __nv_bfloat16 h0 = __float2bfloat16_rn(v.x);
    __nv_bfloat16 h1 = __float2bfloat16_rn(v.y);
    __nv_bfloat16 l0 = __float2bfloat16_rn(v.x - __bfloat162float(h0));
    __nv_bfloat16 l1 = __float2bfloat16_rn(v.y - __bfloat162float(h1));
    __nv_bfloat162 H(h0, h1), L(l0, l1);
    hi = *(uint32_t*)&H;
    lo = *(uint32_t*)&L;
}

// ---------------- bf16x3 mma GEMM: x = feat @ W + b --------------------------
// 8 warps; warp = (nh, mq): nh = warp>>2 picks n-half [nh*64, +64),
// mq = warp&3 picks 32-row slab. Warp tile: 32 rows x 64 cols
// (2 m-groups x 8 n-tiles), acc = 64 regs/lane. B smem reads amortize over
// 2 m-groups -> 32 LDS feed 48 MMAs per k-chunk.
extern __shared__ uint32_t sB[];   // [2][128*BPITCH] hi then lo

__global__ __launch_bounds__(256) void k_gemm_mma(const float* __restrict__ feat,
                                                  const uint32_t* __restrict__ gBh,
                                                  const uint32_t* __restrict__ gBl,
                                                  const float* __restrict__ bias,
                                                  float* __restrict__ xout, int n) {
    const int BSZ = 128 * BPITCH;          // 8704 u32
    int tid = threadIdx.x;
    {
        const float4* s1 = (const float4*)gBh;
        const float4* s2 = (const float4*)gBl;
        float4* d1 = (float4*)sB;
        float4* d2 = (float4*)(sB + BSZ);
        for (int i = tid; i < BSZ / 4; i += 256) { d1[i] = __ldg(s1 + i); d2[i] = __ldg(s2 + i); }
    }
    __syncthreads();

    int warp = tid >> 5, lane = tid & 31;
    int nh = warp >> 2;                    // n-half: 0 or 1
    int mq = warp & 3;                     // 32-row slab
    int gid = lane >> 2, tg = lane & 3;

    int rbase = blockIdx.x * 128 + mq * 32;
    // rows per m-group g: rbase + g*16 + gid, +8
    int rows[4];                            // g0r0, g0r1, g1r0, g1r1
#pragma unroll
    for (int g = 0; g < 2; g++) {
        rows[2 * g + 0] = rbase + g * 16 + gid;
        rows[2 * g + 1] = rbase + g * 16 + 8 + gid;
    }
    const float* Aptr[4];
#pragma unroll
    for (int j = 0; j < 4; j++) {
        int rr = (rows[j] < n) ? rows[j] : (n - 1);
        Aptr[j] = feat + (size_t)rr * C;
    }

    float acc[2][8][4];
#pragma unroll
    for (int g = 0; g < 2; g++)
#pragma unroll
        for (int t = 0; t < 8; t++) { acc[g][t][0] = acc[g][t][1] = acc[g][t][2] = acc[g][t][3] = 0.0f; }

    const uint32_t* Bh = sB;
    const uint32_t* Bl = sB + BSZ;

#pragma unroll
    for (int ch = 0; ch < 8; ch++) {
        int k0 = ch * 16 + tg * 2;
        uint32_t ah[2][4], al[2][4];
#pragma unroll
        for (int g = 0; g < 2; g++) {
            float2 p0 = __ldg((const float2*)(Aptr[2 * g + 0] + k0));
            float2 p1 = __ldg((const float2*)(Aptr[2 * g + 1] + k0));
            float2 p2 = __ldg((const float2*)(Aptr[2 * g + 0] + k0 + 8));
            float2 p3 = __ldg((const float2*)(Aptr[2 * g + 1] + k0 + 8));
            cvt2(p0, ah[g][0], al[g][0]);
            cvt2(p1, ah[g][1], al[g][1]);
            cvt2(p2, ah[g][2], al[g][2]);
            cvt2(p3, ah[g][3], al[g][3]);
        }
        int bbase = ch * 8 + tg;
#pragma unroll
        for (int t = 0; t < 8; t++) {
            int nrow = nh * 64 + t * 8 + gid;
            int ci = nrow * BPITCH + bbase;
            uint32_t bh0 = Bh[ci], bh1 = Bh[ci + 4];
            uint32_t bl0 = Bl[ci], bl1 = Bl[ci + 4];
#pragma unroll
            for (int g = 0; g < 2; g++) {
                mma16816(acc[g][t], ah[g], bh0, bh1);
                mma16816(acc[g][t], ah[g], bl0, bl1);
                mma16816(acc[g][t], al[g], bh0, bh1);
            }
        }
    }

    // epilogue: +bias, float2 stores
#pragma unroll
    for (int t = 0; t < 8; t++) {
        int c0 = nh * 64 + t * 8 + tg * 2;
        float2 bv = __ldg((const float2*)(bias + c0));
#pragma unroll
        for (int g = 0; g < 2; g++) {
            int ra = rows[2 * g + 0], rb = rows[2 * g + 1];
            if (ra < n) {
                float2 o = make_float2(acc[g][t][0] + bv.x, acc[g][t][1] + bv.y);
                *(float2*)(xout + (size_t)ra * C + c0) = o;
            }
            if (rb < n) {
                float2 o = make_float2(acc[g][t][2] + bv.x, acc[g][t][3] + bv.y);
                *(float2*)(xout + (size_t)rb * C + c0) = o;
            }
        }
    }
}

// ---------------- two-level exclusive scan over deg --------------------------
__global__ __launch_bounds__(256) void k_scan_block(const int* __restrict__ deg,
                                                    int* __restrict__ scan,
                                                    int* __restrict__ part, int n) {
    __shared__ int sd[256];
    int t = threadIdx.x;
    int base = blockIdx.x * 1024 + t * 4;
    int d0 = (base + 0 < n) ? deg[base + 0] : 0;
    int d1 = (base + 1 < n) ? deg[base + 1] : 0;
    int d2 = (base + 2 < n) ? deg[base + 2] : 0;
    int d3 = (base + 3 < n) ? deg[base + 3] : 0;
    int s = d0 + d1 + d2 + d3;
    sd[t] = s;
#pragma unroll
    for (int off = 1; off < 256; off <<= 1) {
        __syncthreads();
        int v = (t >= off) ? sd[t - off] : 0;
        __syncthreads();
        sd[t] += v;
    }
    __syncthreads();
    int excl = sd[t] - s;
    if (base + 0 < n) scan[base + 0] = excl;
    if (base + 1 < n) scan[base + 1] = excl + d0;
    if (base + 2 < n) scan[base + 2] = excl + d0 + d1;
    if (base + 3 < n) scan[base + 3] = excl + d0 + d1 + d2;
    if (t == 255) part[blockIdx.x] = sd[255];
}

__global__ void k_scan_part(const int* __restrict__ part, int* __restrict__ partscan,
                            int nb) {
    __shared__ int sd[128];
    int t = threadIdx.x;
    int s = (t < nb) ? part[t] : 0;
    sd[t] = s;
#pragma unroll
    for (int off = 1; off < 128; off <<= 1) {
        __syncthreads();
        int v = (t >= off) ? sd[t - off] : 0;
        __syncthreads();
        sd[t] += v;
    }
    __syncthreads();
    if (t < nb) partscan[t] = sd[t] - s;
}

__global__ void k_scan_add(const int* __restrict__ scan, const int* __restrict__ partscan,
                           int* __restrict__ start, int* __restrict__ cursor,
                           int n, int E) {
    int i = blockIdx.x * blockDim.x + threadIdx.x;
    if (i < n) {
        int v = scan[i] + partscan[i >> 10];
        start[i] = v;
        cursor[i] = v;
    }
    if (i == 0) start[n] = E;
}

// ---------------- per-edge weight + direct CSR fill --------------------------
__global__ __launch_bounds__(256) void k_edge_w(const int* __restrict__ edges,
                                                const float* __restrict__ verts,
                                                const float* __restrict__ nacc,
                                                const float* __restrict__ W1,
                                                const float* __restrict__ b1,
                                                const float* __restrict__ W2,
                                                const float* __restrict__ b2,
                                                int* __restrict__ cursor,
                                                int* __restrict__ csr_src,
                                                float* __restrict__ csr_w, int E) {
    __shared__ float sW1[96];
    __shared__ float sb1[32];
    __shared__ float sW2[192];
    __shared__ float sb2[6];
    int tid = threadIdx.x;
    for (int i = tid; i < 96;  i += blockDim.x) sW1[i] = W1[i];
    for (int i = tid; i < 32;  i += blockDim.x) sb1[i] = b1[i];
    for (int i = tid; i < 192; i += blockDim.x) sW2[i] = W2[i];
    for (int i = tid; i < 6;   i += blockDim.x) sb2[i] = b2[i];
    __syncthreads();

    int e = blockIdx.x * blockDim.x + tid;
    if (e >= E) return;
    int src = __ldg(edges + e);
    int dst = __ldg(edges + E + e);

    float dx = __ldg(verts + 3 * dst)     - __ldg(verts + 3 * src);
    float dy = __ldg(verts + 3 * dst + 1) - __ldg(verts + 3 * src + 1);
    float dz = __ldg(verts + 3 * dst + 2) - __ldg(verts + 3 * src + 2);
    float rx = __ldg(nacc + 3 * src), ry = __ldg(nacc + 3 * src + 1), rz = __ldg(nacc + 3 * src + 2);
    float len = sqrtf(rx * rx + ry * ry + rz * rz);
    float inv = 1.0f / (len + 1e-8f);
    float nx = rx * inv, ny = ry * inv, nz = rz * inv;

    float dot = dx * nx + dy * ny + dz * nz;
    float t0 = dx - dot * nx, t1 = dy - dot * ny, t2 = dz - dot * nz;

    float th[6];
#pragma unroll
    for (int m = 0; m < 6; m++) th[m] = sb2[m];
#pragma unroll
    for (int j = 0; j < 32; j++) {
        float h = sb1[j] + t0 * sW1[j] + t1 * sW1[32 + j] + t2 * sW1[64 + j];
        h = fmaxf(h, 0.0f);
#pragma unroll
        for (int m = 0; m < 6; m++) th[m] += h * sW2[j * 6 + m];
    }
    float s0 = th[0] * t0 + th[1] * t1 + th[2] * t2;
    float s1 = th[1] * t0 + th[3] * t1 + th[4] * t2;
    float s2 = th[2] * t0 + th[4] * t1 + th[5] * t2;
    float q = s0 * s0 + s1 * s1 + s2 * s2;
    float wv = expf(-q);

    int pos = atomicAdd(&cursor[dst], 1);
    csr_src[pos] = src;
    csr_w[pos] = wv;
}

// ---------------- gather aggregation: warp per dst vertex, 4-wide MLP --------
__global__ __launch_bounds__(256) void k_gather(const int* __restrict__ start,
                                                const int* __restrict__ csr_src,
                                                const float* __restrict__ csr_w,
                                                const float* __restrict__ x,
                                                float* __restrict__ p, int n) {
    int v = (blockIdx.x * blockDim.x + threadIdx.x) >> 5;
    int lane = threadIdx.x & 31;
    if (v >= n) return;
    int beg = __ldg(start + v);
    int end = __ldg(start + v + 1);
    float4 acc = make_float4(0.f, 0.f, 0.f, 0.f);
    float dsum = 0.0f;
    int i = beg;
    for (; i + 4 <= end; i += 4) {
        int s0 = __ldg(csr_src + i + 0);
        int s1 = __ldg(csr_src + i + 1);
        int s2 = __ldg(csr_src + i + 2);
        int s3 = __ldg(csr_src + i + 3);
        float w0 = __ldg(csr_w + i + 0);
        float w1 = __ldg(csr_w + i + 1);
        float w2 = __ldg(csr_w + i + 2);
        float w3 = __ldg(csr_w + i + 3);
        float4 a = __ldg((const float4*)(x + (size_t)s0 * C) + lane);
        float4 b = __ldg((const float4*)(x + (size_t)s1 * C) + lane);
        float4 c = __ldg((const float4*)(x + (size_t)s2 * C) + lane);
        float4 d = __ldg((const float4*)(x + (size_t)s3 * C) + lane);
        dsum += (w0 + w1) + (w2 + w3);
        acc.x += w0 * a.x + w1 * b.x + w2 * c.x + w3 * d.x;
        acc.y += w0 * a.y + w1 * b.y + w2 * c.y + w3 * d.y;
        acc.z += w0 * a.z + w1 * b.z + w2 * c.z + w3 * d.z;
        acc.w += w0 * a.w + w1 * b.w + w2 * c.w + w3 * d.w;
    }
    for (; i < end; i++) {
        int s = __ldg(csr_src + i);
        float we = __ldg(csr_w + i);
        float4 xv = __ldg((const float4*)(x + (size_t)s * C) + lane);
        dsum += we;
        acc.x += we * xv.x; acc.y += we * xv.y; acc.z += we * xv.z; acc.w += we * xv.w;
    }
    float rd = 1.0f / (dsum + 1e-5f);
    acc.x *= rd; acc.y *= rd; acc.z *= rd; acc.w *= rd;
    *((float4*)(p + (size_t)v * C) + lane) = acc;
}

// ---------------- per-column stats -------------------------------------------
__global__ void k_stats(const float* __restrict__ p, float* __restrict__ stats, int n) {
    int c = threadIdx.x;  // 128 threads
    float s1 = 0.0f, s2 = 0.0f;
    for (int r = blockIdx.x; r < n; r += gridDim.x) {
        float v = __ldg(p + (size_t)r * C + c);
        s1 += v;
        s2 += v * v;
    }
    atomicAdd(&stats[c], s1);
    atomicAdd(&stats[C + c], s2);
}

// ---------------- final: (inline mu/rstd) normalize + ELU, float4 ------------
__global__ __launch_bounds__(256) void k_final(const float* __restrict__ p,
                                               const float* __restrict__ stats,
                                               float* __restrict__ out, int n) {
    __shared__ float smu[C];
    __shared__ float srstd[C];
    int tid = threadIdx.x;
    if (tid < C) {
        float m = stats[tid] / (float)n;
        float var = (stats[C + tid] - (float)n * m * m) / (float)(n - 1);
        var = fmaxf(var, 0.0f);
        smu[tid] = m;
        srstd[tid] = 1.0f / (sqrtf(var) + 1e-5f);
    }
    __syncthreads();
    size_t i4 = (size_t)blockIdx.x * blockDim.x + tid;    // float4 index
    if (i4 >= (size_t)n * 32) return;
    int c4 = (int)(i4 & 31) * 4;
    float4 v = __ldg((const float4*)p + i4);
    float y0 = (v.x - smu[c4 + 0]) * srstd[c4 + 0];
    float y1 = (v.y - smu[c4 + 1]) * srstd[c4 + 1];
    float y2 = (v.z - smu[c4 + 2]) * srstd[c4 + 2];
    float y3 = (v.w - smu[c4 + 3]) * srstd[c4 + 3];
    float4 o;
    o.x = (y0 > 0.0f) ? y0 : expm1f(y0);
    o.y = (y1 > 0.0f) ? y1 : expm1f(y1);
    o.z = (y2 > 0.0f) ? y2 : expm1f(y2);
    o.w = (y3 > 0.0f) ? y3 : expm1f(y3);
    ((float4*)out)[i4] = o;
}

// ---------------- launch -----------------------------------------------------
extern "C" void kernel_launch(void* const* d_in, const int* in_sizes, int n_in,
                              void* d_out, int out_size) {
    const float* features = (const float*)d_in[0];
    const float* vertices = (const float*)d_in[1];
    const int*   edges    = (const int*)d_in[2];
    const int*   faces    = (const int*)d_in[3];
    const float* W1       = (const float*)d_in[4];
    const float* b1       = (const float*)d_in[5];
    const float* W2       = (const float*)d_in[6];
    const float* b2       = (const float*)d_in[7];
    const float* Wlin     = (const float*)d_in[8];
    const float* blin     = (const float*)d_in[9];

    int n = in_sizes[0] / C;
    int e = in_sizes[2] / 2;
    int f = in_sizes[3] / 3;
    if (n > NMAX) n = NMAX;
    if (e > EMAX) e = EMAX;
    if (f > FMAX) f = FMAX;

    float *p_x, *p_p, *p_nacc, *p_stats, *p_csrw;
    int *p_deg, *p_scan, *p_part, *p_partscan, *p_start, *p_cursor, *p_csrsrc;
    uint32_t *p_bh, *p_bl;
    cudaGetSymbolAddress((void**)&p_x, g_x);
    cudaGetSymbolAddress((void**)&p_p, g_p);
    cudaGetSymbolAddress((void**)&p_nacc, g_nacc);
    cudaGetSymbolAddress((void**)&p_stats, g_stats);
    cudaGetSymbolAddress((void**)&p_deg, g_deg);
    cudaGetSymbolAddress((void**)&p_scan, g_scan);
    cudaGetSymbolAddress((void**)&p_part, g_part);
    cudaGetSymbolAddress((void**)&p_partscan, g_partscan);
    cudaGetSymbolAddress((void**)&p_start, g_start);
    cudaGetSymbolAddress((void**)&p_cursor, g_cursor);
    cudaGetSymbolAddress((void**)&p_csrsrc, g_csr_src);
    cudaGetSymbolAddress((void**)&p_csrw, g_csr_w);
    cudaGetSymbolAddress((void**)&p_bh, g_Bh);
    cudaGetSymbolAddress((void**)&p_bl, g_Bl);

    float* out = (float*)d_out;

    const int GEMM_SMEM = 2 * 128 * BPITCH * 4;   // 69632 bytes
    cudaFuncSetAttribute(k_gemm_mma, cudaFuncAttributeMaxDynamicSharedMemorySize, GEMM_SMEM);

    int nb = (n + 1023) / 1024;                   // scan blocks (<=128)

    k_prepB<<<32, 256>>>(Wlin, p_bh, p_bl);                                        // 0
    k_zero_misc<<<(n * 3 + 255) / 256, 256>>>(p_nacc, p_deg, p_stats, n);          // 1
    k_face_count<<<(f + e + 255) / 256, 256>>>(faces, vertices, edges, p_nacc,
                                               p_deg, f, e);                       // 2
    k_gemm_mma<<<(n + 127) / 128, 256, GEMM_SMEM>>>(features, p_bh, p_bl,
                                                    blin, p_x, n);                 // 3 (ncu)
    k_scan_block<<<nb, 256>>>(p_deg, p_scan, p_part, n);                           // 4
    k_scan_part<<<1, 128>>>(p_part, p_partscan, nb);                               // 5
    k_scan_add<<<(n + 255) / 256, 256>>>(p_scan, p_partscan, p_start, p_cursor, n, e); // 6
    k_edge_w<<<(e + 255) / 256, 256>>>(edges, vertices, p_nacc, W1, b1, W2, b2,
                                       p_cursor, p_csrsrc, p_csrw, e);             // 7
    k_gather<<<(n * 32 + 255) / 256, 256>>>(p_start, p_csrsrc, p_csrw, p_x, p_p, n); // 8
    k_stats<<<512, 128>>>(p_p, p_stats, n);                                        // 9
    k_final<<<(n * 32 + 255) / 256, 256>>>(p_p, p_stats, out, n);                  // 10
}

// round 12
// speedup vs baseline: 1.4079x; 1.4079x over previous
#include <cuda_runtime.h>
#include <cuda_bf16.h>
#include <cstdint>
#include <cstddef>

#define NMAX 100000
#define EMAX 600000
#define FMAX 200000
#define C    128

// ---------------- scratch (static device globals; no runtime alloc) ----------
__device__ float g_x[(size_t)NMAX * C];      // features @ Wlin + blin
__device__ float g_p[(size_t)NMAX * C];      // aggregated & den-normalized rows
__device__ float g_nacc[NMAX * 3];           // accumulated face normals (raw)
__device__ float g_stats[256];               // colsum[128], colsum2[128]
// CSR-by-dst
__device__ int   g_deg[NMAX];
__device__ int   g_scan[NMAX];               // in-block exclusive scan
__device__ int   g_part[128];                // block partial sums
__device__ int   g_partscan[128];
__device__ int   g_start[NMAX + 1];
__device__ int   g_cursor[NMAX];
__device__ int   g_csr_src[EMAX];
__device__ float g_csr_w[EMAX];
// pre-converted W as bf16 hi/lo pairs, layout [n][k-pair] with pitch 68 u32
#define BPITCH 68
__device__ uint32_t g_Bh[128 * BPITCH];
__device__ uint32_t g_Bl[128 * BPITCH];

// ---------------- W pre-convert: fp32 -> bf16 hi/lo [n][k] pitch-68 ----------
__global__ void k_prepB(const float* __restrict__ W, uint32_t* __restrict__ bh,
                        uint32_t* __restrict__ bl) {
    int idx = blockIdx.x * blockDim.x + threadIdx.x;   // 128 cols * 64 k-pairs
    if (idx >= 128 * 64) return;
    int c = idx >> 6, kp = idx & 63;
    float v0 = __ldg(W + (size_t)(2 * kp) * C + c);
    float v1 = __ldg(W + (size_t)(2 * kp + 1) * C + c);
    __nv_bfloat16 h0 = __float2bfloat16_rn(v0);
    __nv_bfloat16 h1 = __float2bfloat16_rn(v1);
    __nv_bfloat16 l0 = __float2bfloat16_rn(v0 - __bfloat162float(h0));
    __nv_bfloat16 l1 = __float2bfloat16_rn(v1 - __bfloat162float(h1));
    __nv_bfloat162 H(h0, h1), L(l0, l1);
    bh[c * BPITCH + kp] = *(uint32_t*)&H;
    bl[c * BPITCH + kp] = *(uint32_t*)&L;
}

// ---------------- zero helper ------------------------------------------------
__global__ void k_zero_misc(float* __restrict__ nacc, int* __restrict__ deg,
                            float* __restrict__ stats, int n) {
    int i = blockIdx.x * blockDim.x + threadIdx.x;
    if (i < n * 3) nacc[i] = 0.0f;
    if (i < n) deg[i] = 0;
    if (i < 256) stats[i] = 0.0f;
}

// ---------------- face normals (scatter) + dst degree count ------------------
__global__ void k_face_count(const int* __restrict__ faces, const float* __restrict__ verts,
                             const int* __restrict__ edges, float* __restrict__ nacc,
                             int* __restrict__ deg, int F, int E) {
    int t = blockIdx.x * blockDim.x + threadIdx.x;
    if (t < F) {
        int f = t;
        int i0 = __ldg(faces + f);
        int i1 = __ldg(faces + F + f);
        int i2 = __ldg(faces + 2 * F + f);
        float v0x = __ldg(verts + 3 * i0), v0y = __ldg(verts + 3 * i0 + 1), v0z = __ldg(verts + 3 * i0 + 2);
        float v1x = __ldg(verts + 3 * i1), v1y = __ldg(verts + 3 * i1 + 1), v1z = __ldg(verts + 3 * i1 + 2);
        float v2x = __ldg(verts + 3 * i2), v2y = __ldg(verts + 3 * i2 + 1), v2z = __ldg(verts + 3 * i2 + 2);
        float ax = v1x - v0x, ay = v1y - v0y, az = v1z - v0z;
        float bx = v2x - v0x, by = v2y - v0y, bz = v2z - v0z;
        float nx = ay * bz - az * by;
        float ny = az * bx - ax * bz;
        float nz = ax * by - ay * bx;
        atomicAdd(&nacc[3 * i0 + 0], nx); atomicAdd(&nacc[3 * i0 + 1], ny); atomicAdd(&nacc[3 * i0 + 2], nz);
        atomicAdd(&nacc[3 * i1 + 0], nx); atomicAdd(&nacc[3 * i1 + 1], ny); atomicAdd(&nacc[3 * i1 + 2], nz);
        atomicAdd(&nacc[3 * i2 + 0], nx); atomicAdd(&nacc[3 * i2 + 1], ny); atomicAdd(&nacc[3 * i2 + 2], nz);
    } else {
        int e = t - F;
        if (e < E) atomicAdd(&deg[__ldg(edges + E + e)], 1);
    }
}

// ---------------- mma.sync helpers -------------------------------------------
__device__ __forceinline__ void mma16816(float* c, const uint32_t* a,
                                         uint32_t b0, uint32_t b1) {
    asm volatile(
        "mma.sync.aligned.m16n8k16.row.col.f32.bf16.bf16.f32 "
        "{%0,%1,%2,%3}, {%4,%5,%6,%7}, {%8,%9}, {%0,%1,%2,%3};"
        : "+f"(c[0]), "+f"(c[1]), "+f"(c[2]), "+f"(c[3])
        : "r"(a[0]), "r"(a[1]), "r"(a[2]), "r"(a[3]), "r"(b0), "r"(b1));
}

__device__ __forceinline__ void cvt2(float2 v, uint32_t& hi, uint32_t& lo) {
    __nv_bfloat16 h0 = __float2bfloat16_rn(v.x);
    __nv_bfloat16 h1 = __float2bfloat16_rn(v.y);
    __nv_bfloat16 l0 = __float2bfloat16_rn(v.x - __bfloat162float(h0));
    __nv_bfloat16 l1 = __float2bfloat16_rn(v.y - __bfloat162float(h1));
    __nv_bfloat162 H(h0, h1), L(l0, l1);
    hi = *(uint32_t*)&H;
    lo = *(uint32_t*)&L;
}

// ---------------- bf16x3 mma GEMM: x = feat @ W + b --------------------------
// 8 warps; warp = (nh, mq): warp tile 32 rows x 64 cols (2 m-groups x 8
// n-tiles). B smem reads amortize over 2 m-groups. __launch_bounds__(256,2)
// clamps regs to <=128 so 2 CTAs/SM are guaranteed (round-11 regression was
// 146 regs -> 1 CTA/SM -> latency exposure).
extern __shared__ uint32_t sB[];   // [2][128*BPITCH] hi then lo

__global__ __launch_bounds__(256, 2) void k_gemm_mma(const float* __restrict__ feat,
                                                     const uint32_t* __restrict__ gBh,
                                                     const uint32_t* __restrict__ gBl,
                                                     const float* __restrict__ bias,
                                                     float* __restrict__ xout, int n) {
    const int BSZ = 128 * BPITCH;          // 8704 u32
    int tid = threadIdx.x;
    {
        const float4* s1 = (const float4*)gBh;
        const float4* s2 = (const float4*)gBl;
        float4* d1 = (float4*)sB;
        float4* d2 = (float4*)(sB + BSZ);
        for (int i = tid; i < BSZ / 4; i += 256) { d1[i] = __ldg(s1 + i); d2[i] = __ldg(s2 + i); }
    }
    __syncthreads();

    int warp = tid >> 5, lane = tid & 31;
    int nh = warp >> 2;                    // n-half: 0 or 1
    int mq = warp & 3;                     // 32-row slab
    int gid = lane >> 2, tg = lane & 3;

    int rbase = blockIdx.x * 128 + mq * 32;
    int rows[4];                            // g0r0, g0r1, g1r0, g1r1
#pragma unroll
    for (int g = 0; g < 2; g++) {
        rows[2 * g + 0] = rbase + g * 16 + gid;
        rows[2 * g + 1] = rbase + g * 16 + 8 + gid;
    }
    const float* Aptr[4];
#pragma unroll
    for (int j = 0; j < 4; j++) {
        int rr = (rows[j] < n) ? rows[j] : (n - 1);
        Aptr[j] = feat + (size_t)rr * C;
    }

    float acc[2][8][4];
#pragma unroll
    for (int g = 0; g < 2; g++)
#pragma unroll
        for (int t = 0; t < 8; t++) { acc[g][t][0] = acc[g][t][1] = acc[g][t][2] = acc[g][t][3] = 0.0f; }

    const uint32_t* Bh = sB;
    const uint32_t* Bl = sB + BSZ;

#pragma unroll
    for (int ch = 0; ch < 8; ch++) {
        int k0 = ch * 16 + tg * 2;
        uint32_t ah[2][4], al[2][4];
#pragma unroll
        for (int g = 0; g < 2; g++) {
            float2 p0 = __ldg((const float2*)(Aptr[2 * g + 0] + k0));
            float2 p1 = __ldg((const float2*)(Aptr[2 * g + 1] + k0));
            float2 p2 = __ldg((const float2*)(Aptr[2 * g + 0] + k0 + 8));
            float2 p3 = __ldg((const float2*)(Aptr[2 * g + 1] + k0 + 8));
            cvt2(p0, ah[g][0], al[g][0]);
            cvt2(p1, ah[g][1], al[g][1]);
            cvt2(p2, ah[g][2], al[g][2]);
            cvt2(p3, ah[g][3], al[g][3]);
        }
        int bbase = ch * 8 + tg;
#pragma unroll
        for (int t = 0; t < 8; t++) {
            int nrow = nh * 64 + t * 8 + gid;
            int ci = nrow * BPITCH + bbase;
            uint32_t bh0 = Bh[ci], bh1 = Bh[ci + 4];
            uint32_t bl0 = Bl[ci], bl1 = Bl[ci + 4];
#pragma unroll
            for (int g = 0; g < 2; g++) {
                mma16816(acc[g][t], ah[g], bh0, bh1);
                mma16816(acc[g][t], ah[g], bl0, bl1);
                mma16816(acc[g][t], al[g], bh0, bh1);
            }
        }
    }

    // epilogue: +bias, float2 stores
#pragma unroll
    for (int t = 0; t < 8; t++) {
        int c0 = nh * 64 + t * 8 + tg * 2;
        float2 bv = __ldg((const float2*)(bias + c0));
#pragma unroll
        for (int g = 0; g < 2; g++) {
            int ra = rows[2 * g + 0], rb = rows[2 * g + 1];
            if (ra < n) {
                float2 o = make_float2(acc[g][t][0] + bv.x, acc[g][t][1] + bv.y);
                *(float2*)(xout + (size_t)ra * C + c0) = o;
            }
            if (rb < n) {
                float2 o = make_float2(acc[g][t][2] + bv.x, acc[g][t][3] + bv.y);
                *(float2*)(xout + (size_t)rb * C + c0) = o;
            }
        }
    }
}

// ---------------- two-level exclusive scan over deg --------------------------
__global__ __launch_bounds__(256) void k_scan_block(const int* __restrict__ deg,
                                                    int* __restrict__ scan,
                                                    int* __restrict__ part, int n) {
    __shared__ int sd[256];
    int t = threadIdx.x;
    int base = blockIdx.x * 1024 + t * 4;
    int d0 = (base + 0 < n) ? deg[base + 0] : 0;
    int d1 = (base + 1 < n) ? deg[base + 1] : 0;
    int d2 = (base + 2 < n) ? deg[base + 2] : 0;
    int d3 = (base + 3 < n) ? deg[base + 3] : 0;
    int s = d0 + d1 + d2 + d3;
    sd[t] = s;
#pragma unroll
    for (int off = 1; off < 256; off <<= 1) {
        __syncthreads();
        int v = (t >= off) ? sd[t - off] : 0;
        __syncthreads();
        sd[t] += v;
    }
    __syncthreads();
    int excl = sd[t] - s;
    if (base + 0 < n) scan[base + 0] = excl;
    if (base + 1 < n) scan[base + 1] = excl + d0;
    if (base + 2 < n) scan[base + 2] = excl + d0 + d1;
    if (base + 3 < n) scan[base + 3] = excl + d0 + d1 + d2;
    if (t == 255) part[blockIdx.x] = sd[255];
}

__global__ void k_scan_part(const int* __restrict__ part, int* __restrict__ partscan,
                            int nb) {
    __shared__ int sd[128];
    int t = threadIdx.x;
    int s = (t < nb) ? part[t] : 0;
    sd[t] = s;
#pragma unroll
    for (int off = 1; off < 128; off <<= 1) {
        __syncthreads();
        int v = (t >= off) ? sd[t - off] : 0;
        __syncthreads();
        sd[t] += v;
    }
    __syncthreads();
    if (t < nb) partscan[t] = sd[t] - s;
}

__global__ void k_scan_add(const int* __restrict__ scan, const int* __restrict__ partscan,
                           int* __restrict__ start, int* __restrict__ cursor,
                           int n, int E) {
    int i = blockIdx.x * blockDim.x + threadIdx.x;
    if (i < n) {
        int v = scan[i] + partscan[i >> 10];
        start[i] = v;
        cursor[i] = v;
    }
    if (i == 0) start[n] = E;
}

// ---------------- per-edge weight + direct CSR fill --------------------------
__global__ __launch_bounds__(256) void k_edge_w(const int* __restrict__ edges,
                                                const float* __restrict__ verts,
                                                const float* __restrict__ nacc,
                                                const float* __restrict__ W1,
                                                const float* __restrict__ b1,
                                                const float* __restrict__ W2,
                                                const float* __restrict__ b2,
                                                int* __restrict__ cursor,
                                                int* __restrict__ csr_src,
                                                float* __restrict__ csr_w, int E) {
    __shared__ float sW1[96];
    __shared__ float sb1[32];
    __shared__ float sW2[192];
    __shared__ float sb2[6];
    int tid = threadIdx.x;
    for (int i = tid; i < 96;  i += blockDim.x) sW1[i] = W1[i];
    for (int i = tid; i < 32;  i += blockDim.x) sb1[i] = b1[i];
    for (int i = tid; i < 192; i += blockDim.x) sW2[i] = W2[i];
    for (int i = tid; i < 6;   i += blockDim.x) sb2[i] = b2[i];
    __syncthreads();

    int e = blockIdx.x * blockDim.x + tid;
    if (e >= E) return;
    int src = __ldg(edges + e);
    int dst = __ldg(edges + E + e);

    float dx = __ldg(verts + 3 * dst)     - __ldg(verts + 3 * src);
    float dy = __ldg(verts + 3 * dst + 1) - __ldg(verts + 3 * src + 1);
    float dz = __ldg(verts + 3 * dst + 2) - __ldg(verts + 3 * src + 2);
    float rx = __ldg(nacc + 3 * src), ry = __ldg(nacc + 3 * src + 1), rz = __ldg(nacc + 3 * src + 2);
    float len = sqrtf(rx * rx + ry * ry + rz * rz);
    float inv = 1.0f / (len + 1e-8f);
    float nx = rx * inv, ny = ry * inv, nz = rz * inv;

    float dot = dx * nx + dy * ny + dz * nz;
    float t0 = dx - dot * nx, t1 = dy - dot * ny, t2 = dz - dot * nz;

    float th[6];
#pragma unroll
    for (int m = 0; m < 6; m++) th[m] = sb2[m];
#pragma unroll
    for (int j = 0; j < 32; j++) {
        float h = sb1[j] + t0 * sW1[j] + t1 * sW1[32 + j] + t2 * sW1[64 + j];
        h = fmaxf(h, 0.0f);
#pragma unroll
        for (int m = 0; m < 6; m++) th[m] += h * sW2[j * 6 + m];
    }
    float s0 = th[0] * t0 + th[1] * t1 + th[2] * t2;
    float s1 = th[1] * t0 + th[3] * t1 + th[4] * t2;
    float s2 = th[2] * t0 + th[4] * t1 + th[5] * t2;
    float q = s0 * s0 + s1 * s1 + s2 * s2;
    float wv = expf(-q);

    int pos = atomicAdd(&cursor[dst], 1);
    csr_src[pos] = src;
    csr_w[pos] = wv;
}

// ---------------- gather + fused column stats --------------------------------
// block = 8 warps; each warp handles 8 vertices (block covers 64). Per-lane
// register partial sums for its 4 columns; block reduce in smem; one
// atomicAdd per column per block (1563 blocks).
__global__ __launch_bounds__(256) void k_gather_stats(const int* __restrict__ start,
                                                      const int* __restrict__ csr_src,
                                                      const float* __restrict__ csr_w,
                                                      const float* __restrict__ x,
                                                      float* __restrict__ p,
                                                      float* __restrict__ stats, int n) {
    int warp = threadIdx.x >> 5, lane = threadIdx.x & 31;
    float4 s1 = make_float4(0.f, 0.f, 0.f, 0.f);
    float4 s2 = make_float4(0.f, 0.f, 0.f, 0.f);

    for (int it = 0; it < 8; it++) {
        int v = blockIdx.x * 64 + it * 8 + warp;
        if (v >= n) break;
        int beg = __ldg(start + v);
        int end = __ldg(start + v + 1);
        float4 acc = make_float4(0.f, 0.f, 0.f, 0.f);
        float dsum = 0.0f;
        int i = beg;
        for (; i + 4 <= end; i += 4) {
            int e0 = __ldg(csr_src + i + 0);
            int e1 = __ldg(csr_src + i + 1);
            int e2 = __ldg(csr_src + i + 2);
            int e3 = __ldg(csr_src + i + 3);
            float w0 = __ldg(csr_w + i + 0);
            float w1 = __ldg(csr_w + i + 1);
            float w2 = __ldg(csr_w + i + 2);
            float w3 = __ldg(csr_w + i + 3);
            float4 a = __ldg((const float4*)(x + (size_t)e0 * C) + lane);
            float4 b = __ldg((const float4*)(x + (size_t)e1 * C) + lane);
            float4 c = __ldg((const float4*)(x + (size_t)e2 * C) + lane);
            float4 d = __ldg((const float4*)(x + (size_t)e3 * C) + lane);
            dsum += (w0 + w1) + (w2 + w3);
            acc.x += w0 * a.x + w1 * b.x + w2 * c.x + w3 * d.x;
            acc.y += w0 * a.y + w1 * b.y + w2 * c.y + w3 * d.y;
            acc.z += w0 * a.z + w1 * b.z + w2 * c.z + w3 * d.z;
            acc.w += w0 * a.w + w1 * b.w + w2 * c.w + w3 * d.w;
        }
        for (; i < end; i++) {
            int s = __ldg(csr_src + i);
            float we = __ldg(csr_w + i);
            float4 xv = __ldg((const float4*)(x + (size_t)s * C) + lane);
            dsum += we;
            acc.x += we * xv.x; acc.y += we * xv.y; acc.z += we * xv.z; acc.w += we * xv.w;
        }
        float rd = 1.0f / (dsum + 1e-5f);
        acc.x *= rd; acc.y *= rd; acc.z *= rd; acc.w *= rd;
        *((float4*)(p + (size_t)v * C) + lane) = acc;
        s1.x += acc.x; s1.y += acc.y; s1.z += acc.z; s1.w += acc.w;
        s2.x += acc.x * acc.x; s2.y += acc.y * acc.y; s2.z += acc.z * acc.z; s2.w += acc.w * acc.w;
    }

    __shared__ float4 red[8][32];
    red[warp][lane] = s1;
    __syncthreads();
    if (threadIdx.x < 128) {
        int col = threadIdx.x;
        float s = 0.0f;
#pragma unroll
        for (int w = 0; w < 8; w++) {
            const float* r = (const float*)&red[w][col >> 2];
            s += r[col & 3];
        }
        atomicAdd(&stats[col], s);
    }
    __syncthreads();
    red[warp][lane] = s2;
    __syncthreads();
    if (threadIdx.x < 128) {
        int col = threadIdx.x;
        float s = 0.0f;
#pragma unroll
        for (int w = 0; w < 8; w++) {
            const float* r = (const float*)&red[w][col >> 2];
            s += r[col & 3];
        }
        atomicAdd(&stats[C + col], s);
    }
}

// ---------------- final: (inline mu/rstd) normalize + ELU, float4 ------------
__global__ __launch_bounds__(256) void k_final(const float* __restrict__ p,
                                               const float* __restrict__ stats,
                                               float* __restrict__ out, int n) {
    __shared__ float smu[C];
    __shared__ float srstd[C];
    int tid = threadIdx.x;
    if (tid < C) {
        float m = stats[tid] / (float)n;
        float var = (stats[C + tid] - (float)n * m * m) / (float)(n - 1);
        var = fmaxf(var, 0.0f);
        smu[tid] = m;
        srstd[tid] = 1.0f / (sqrtf(var) + 1e-5f);
    }
    __syncthreads();
    size_t i4 = (size_t)blockIdx.x * blockDim.x + tid;    // float4 index
    if (i4 >= (size_t)n * 32) return;
    int c4 = (int)(i4 & 31) * 4;
    float4 v = __ldg((const float4*)p + i4);
    float y0 = (v.x - smu[c4 + 0]) * srstd[c4 + 0];
    float y1 = (v.y - smu[c4 + 1]) * srstd[c4 + 1];
    float y2 = (v.z - smu[c4 + 2]) * srstd[c4 + 2];
    float y3 = (v.w - smu[c4 + 3]) * srstd[c4 + 3];
    float4 o;
    o.x = (y0 > 0.0f) ? y0 : expm1f(y0);
    o.y = (y1 > 0.0f) ? y1 : expm1f(y1);
    o.z = (y2 > 0.0f) ? y2 : expm1f(y2);
    o.w = (y3 > 0.0f) ? y3 : expm1f(y3);
    ((float4*)out)[i4] = o;
}

// ---------------- launch -----------------------------------------------------
extern "C" void kernel_launch(void* const* d_in, const int* in_sizes, int n_in,
                              void* d_out, int out_size) {
    const float* features = (const float*)d_in[0];
    const float* vertices = (const float*)d_in[1];
    const int*   edges    = (const int*)d_in[2];
    const int*   faces    = (const int*)d_in[3];
    const float* W1       = (const float*)d_in[4];
    const float* b1       = (const float*)d_in[5];
    const float* W2       = (const float*)d_in[6];
    const float* b2       = (const float*)d_in[7];
    const float* Wlin     = (const float*)d_in[8];
    const float* blin     = (const float*)d_in[9];

    int n = in_sizes[0] / C;
    int e = in_sizes[2] / 2;
    int f = in_sizes[3] / 3;
    if (n > NMAX) n = NMAX;
    if (e > EMAX) e = EMAX;
    if (f > FMAX) f = FMAX;

    float *p_x, *p_p, *p_nacc, *p_stats, *p_csrw;
    int *p_deg, *p_scan, *p_part, *p_partscan, *p_start, *p_cursor, *p_csrsrc;
    uint32_t *p_bh, *p_bl;
    cudaGetSymbolAddress((void**)&p_x, g_x);
    cudaGetSymbolAddress((void**)&p_p, g_p);
    cudaGetSymbolAddress((void**)&p_nacc, g_nacc);
    cudaGetSymbolAddress((void**)&p_stats, g_stats);
    cudaGetSymbolAddress((void**)&p_deg, g_deg);
    cudaGetSymbolAddress((void**)&p_scan, g_scan);
    cudaGetSymbolAddress((void**)&p_part, g_part);
    cudaGetSymbolAddress((void**)&p_partscan, g_partscan);
    cudaGetSymbolAddress((void**)&p_start, g_start);
    cudaGetSymbolAddress((void**)&p_cursor, g_cursor);
    cudaGetSymbolAddress((void**)&p_csrsrc, g_csr_src);
    cudaGetSymbolAddress((void**)&p_csrw, g_csr_w);
    cudaGetSymbolAddress((void**)&p_bh, g_Bh);
    cudaGetSymbolAddress((void**)&p_bl, g_Bl);

    float* out = (float*)d_out;

    const int GEMM_SMEM = 2 * 128 * BPITCH * 4;   // 69632 bytes
    cudaFuncSetAttribute(k_gemm_mma, cudaFuncAttributeMaxDynamicSharedMemorySize, GEMM_SMEM);

    int nb = (n + 1023) / 1024;                   // scan blocks (<=128)

    k_prepB<<<32, 256>>>(Wlin, p_bh, p_bl);                                        // 0
    k_zero_misc<<<(n * 3 + 255) / 256, 256>>>(p_nacc, p_deg, p_stats, n);          // 1
    k_face_count<<<(f + e + 255) / 256, 256>>>(faces, vertices, edges, p_nacc,
                                               p_deg, f, e);                       // 2
    k_gemm_mma<<<(n + 127) / 128, 256, GEMM_SMEM>>>(features, p_bh, p_bl,
                                                    blin, p_x, n);                 // 3 (ncu)
    k_scan_block<<<nb, 256>>>(p_deg, p_scan, p_part, n);                           // 4
    k_scan_part<<<1, 128>>>(p_part, p_partscan, nb);                               // 5
    k_scan_add<<<(n + 255) / 256, 256>>>(p_scan, p_partscan, p_start, p_cursor, n, e); // 6
    k_edge_w<<<(e + 255) / 256, 256>>>(edges, vertices, p_nacc, W1, b1, W2, b2,
                                       p_cursor, p_csrsrc, p_csrw, e);             // 7
    k_gather_stats<<<(n + 63) / 64, 256>>>(p_start, p_csrsrc, p_csrw, p_x, p_p,
                                           p_stats, n);                            // 8
    k_final<<<(n * 32 + 255) / 256, 256>>>(p_p, p_stats, out, n);                  // 9
}

// round 13
// speedup vs baseline: 1.4122x; 1.0031x over previous
#include <cuda_runtime.h>
#include <cuda_bf16.h>
#include <cstdint>
#include <cstddef>

#define NMAX 100000
#define EMAX 600000
#define FMAX 200000
#define C    128

// ---------------- scratch (static device globals; no runtime alloc) ----------
__device__ float g_x[(size_t)NMAX * C];      // features @ Wlin + blin
__device__ float g_p[(size_t)NMAX * C];      // aggregated & den-normalized rows
__device__ float g_nacc[NMAX * 3];           // accumulated face normals (raw)
__device__ float g_stats[256];               // colsum[128], colsum2[128]
// CSR-by-dst
__device__ int   g_deg[NMAX];
__device__ int   g_scan[NMAX];               // in-block exclusive scan
__device__ int   g_part[128];                // block partial sums
__device__ int   g_partscan[128];
__device__ int   g_start[NMAX + 1];
__device__ int   g_cursor[NMAX];
__device__ int   g_csr_src[EMAX];
__device__ float g_csr_w[EMAX];
// pre-converted W as bf16 hi/lo pairs, layout [n][k-pair] with pitch 68 u32
#define BPITCH 68
__device__ uint32_t g_Bh[128 * BPITCH];
__device__ uint32_t g_Bl[128 * BPITCH];

// ---------------- W pre-convert: fp32 -> bf16 hi/lo [n][k] pitch-68 ----------
__global__ void k_prepB(const float* __restrict__ W, uint32_t* __restrict__ bh,
                        uint32_t* __restrict__ bl) {
    int idx = blockIdx.x * blockDim.x + threadIdx.x;   // 128 cols * 64 k-pairs
    if (idx >= 128 * 64) return;
    int c = idx >> 6, kp = idx & 63;
    float v0 = __ldg(W + (size_t)(2 * kp) * C + c);
    float v1 = __ldg(W + (size_t)(2 * kp + 1) * C + c);
    __nv_bfloat16 h0 = __float2bfloat16_rn(v0);
    __nv_bfloat16 h1 = __float2bfloat16_rn(v1);
    __nv_bfloat16 l0 = __float2bfloat16_rn(v0 - __bfloat162float(h0));
    __nv_bfloat16 l1 = __float2bfloat16_rn(v1 - __bfloat162float(h1));
    __nv_bfloat162 H(h0, h1), L(l0, l1);
    bh[c * BPITCH + kp] = *(uint32_t*)&H;
    bl[c * BPITCH + kp] = *(uint32_t*)&L;
}

// ---------------- zero helper ------------------------------------------------
__global__ void k_zero_misc(float* __restrict__ nacc, int* __restrict__ deg,
                            float* __restrict__ stats, int n) {
    int i = blockIdx.x * blockDim.x + threadIdx.x;
    if (i < n * 3) nacc[i] = 0.0f;
    if (i < n) deg[i] = 0;
    if (i < 256) stats[i] = 0.0f;
}

// ---------------- face normals (scatter) + dst degree count ------------------
__global__ void k_face_count(const int* __restrict__ faces, const float* __restrict__ verts,
                             const int* __restrict__ edges, float* __restrict__ nacc,
                             int* __restrict__ deg, int F, int E) {
    int t = blockIdx.x * blockDim.x + threadIdx.x;
    if (t < F) {
        int f = t;
        int i0 = __ldg(faces + f);
        int i1 = __ldg(faces + F + f);
        int i2 = __ldg(faces + 2 * F + f);
        float v0x = __ldg(verts + 3 * i0), v0y = __ldg(verts + 3 * i0 + 1), v0z = __ldg(verts + 3 * i0 + 2);
        float v1x = __ldg(verts + 3 * i1), v1y = __ldg(verts + 3 * i1 + 1), v1z = __ldg(verts + 3 * i1 + 2);
        float v2x = __ldg(verts + 3 * i2), v2y = __ldg(verts + 3 * i2 + 1), v2z = __ldg(verts + 3 * i2 + 2);
        float ax = v1x - v0x, ay = v1y - v0y, az = v1z - v0z;
        float bx = v2x - v0x, by = v2y - v0y, bz = v2z - v0z;
        float nx = ay * bz - az * by;
        float ny = az * bx - ax * bz;
        float nz = ax * by - ay * bx;
        atomicAdd(&nacc[3 * i0 + 0], nx); atomicAdd(&nacc[3 * i0 + 1], ny); atomicAdd(&nacc[3 * i0 + 2], nz);
        atomicAdd(&nacc[3 * i1 + 0], nx); atomicAdd(&nacc[3 * i1 + 1], ny); atomicAdd(&nacc[3 * i1 + 2], nz);
        atomicAdd(&nacc[3 * i2 + 0], nx); atomicAdd(&nacc[3 * i2 + 1], ny); atomicAdd(&nacc[3 * i2 + 2], nz);
    } else {
        int e = t - F;
        if (e < E) atomicAdd(&deg[__ldg(edges + E + e)], 1);
    }
}

// ---------------- mma.sync helpers -------------------------------------------
__device__ __forceinline__ void mma16816(float* c, const uint32_t* a,
                                         uint32_t b0, uint32_t b1) {
    asm volatile(
        "mma.sync.aligned.m16n8k16.row.col.f32.bf16.bf16.f32 "
        "{%0,%1,%2,%3}, {%4,%5,%6,%7}, {%8,%9}, {%0,%1,%2,%3};"
        : "+f"(c[0]), "+f"(c[1]), "+f"(c[2]), "+f"(c[3])
        : "r"(a[0]), "r"(a[1]), "r"(a[2]), "r"(a[3]), "r"(b0), "r"(b1));
}

__device__ __forceinline__ void cvt2(float2 v, uint32_t& hi, uint32_t& lo) {
    __nv_bfloat16 h0 = __float2bfloat16_rn(v.x);
    __nv_bfloat16 h1 = __float2bfloat16_rn(v.y);
    __nv_bfloat16 l0 = __float2bfloat16_rn(v.x - __bfloat162float(h0));
    __nv_bfloat16 l1 = __float2bfloat16_rn(v.y - __bfloat162float(h1));
    __nv_bfloat162 H(h0, h1), L(l0, l1);
    hi = *(uint32_t*)&H;
    lo = *(uint32_t*)&L;
}

// ---------------- bf16x3 mma GEMM: x = feat @ W + b --------------------------
// Occupancy-first shape: warp tile 16 rows x 64 cols (acc=32 regs). CTA = 8
// warps -> 128 rows x 64 cols; grid.y = 2 selects the n-half, and each CTA
// stages only its half of B (34.8KB smem). launch_bounds(256,3) -> <=85 regs,
// 3 CTAs/SM = 6 warps/SMSP (round-10 was latency-bound at 4/SMSP).
extern __shared__ uint32_t sB[];   // [2][64*BPITCH] hi then lo

__global__ __launch_bounds__(256, 3) void k_gemm_mma(const float* __restrict__ feat,
                                                     const uint32_t* __restrict__ gBh,
                                                     const uint32_t* __restrict__ gBl,
                                                     const float* __restrict__ bias,
                                                     float* __restrict__ xout, int n) {
    const int BSZ = 64 * BPITCH;           // 4352 u32 = 17408 B per matrix
    int tid = threadIdx.x;
    int nh = blockIdx.y;                   // n-half: 0 or 1
    {
        const float4* s1 = (const float4*)(gBh + nh * BSZ);
        const float4* s2 = (const float4*)(gBl + nh * BSZ);
        float4* d1 = (float4*)sB;
        float4* d2 = (float4*)(sB + BSZ);
        for (int i = tid; i < BSZ / 4; i += 256) { d1[i] = __ldg(s1 + i); d2[i] = __ldg(s2 + i); }
    }
    __syncthreads();

    int warp = tid >> 5, lane = tid & 31;
    int gid = lane >> 2, tg = lane & 3;
    int r0 = blockIdx.x * 128 + warp * 16 + gid;
    int r1 = r0 + 8;
    int r0c = (r0 < n) ? r0 : (n - 1);
    int r1c = (r1 < n) ? r1 : (n - 1);
    const float* A0 = feat + (size_t)r0c * C;
    const float* A1 = feat + (size_t)r1c * C;

    float acc[8][4];
#pragma unroll
    for (int t = 0; t < 8; t++) { acc[t][0] = acc[t][1] = acc[t][2] = acc[t][3] = 0.0f; }

    const uint32_t* Bh = sB;
    const uint32_t* Bl = sB + BSZ;

#pragma unroll
    for (int ch = 0; ch < 8; ch++) {
        int k0 = ch * 16 + tg * 2;
        float2 p00 = __ldg((const float2*)(A0 + k0));
        float2 p10 = __ldg((const float2*)(A1 + k0));
        float2 p01 = __ldg((const float2*)(A0 + k0 + 8));
        float2 p11 = __ldg((const float2*)(A1 + k0 + 8));
        uint32_t ah[4], al[4];
        cvt2(p00, ah[0], al[0]);
        cvt2(p10, ah[1], al[1]);
        cvt2(p01, ah[2], al[2]);
        cvt2(p11, ah[3], al[3]);
        int bbase = ch * 8 + tg;
#pragma unroll
        for (int t = 0; t < 8; t++) {
            int ci = (t * 8 + gid) * BPITCH + bbase;     // local n-row within half
            uint32_t bh0 = Bh[ci], bh1 = Bh[ci + 4];
            uint32_t bl0 = Bl[ci], bl1 = Bl[ci + 4];
            mma16816(acc[t], ah, bh0, bh1);
            mma16816(acc[t], ah, bl0, bl1);
            mma16816(acc[t], al, bh0, bh1);
        }
    }

    // epilogue: +bias, float2 stores into this CTA's n-half
#pragma unroll
    for (int t = 0; t < 8; t++) {
        int c0 = nh * 64 + t * 8 + tg * 2;
        float2 bv = __ldg((const float2*)(bias + c0));
        if (r0 < n) {
            float2 o = make_float2(acc[t][0] + bv.x, acc[t][1] + bv.y);
            *(float2*)(xout + (size_t)r0 * C + c0) = o;
        }
        if (r1 < n) {
            float2 o = make_float2(acc[t][2] + bv.x, acc[t][3] + bv.y);
            *(float2*)(xout + (size_t)r1 * C + c0) = o;
        }
    }
}

// ---------------- two-level exclusive scan over deg --------------------------
__global__ __launch_bounds__(256) void k_scan_block(const int* __restrict__ deg,
                                                    int* __restrict__ scan,
                                                    int* __restrict__ part, int n) {
    __shared__ int sd[256];
    int t = threadIdx.x;
    int base = blockIdx.x * 1024 + t * 4;
    int d0 = (base + 0 < n) ? deg[base + 0] : 0;
    int d1 = (base + 1 < n) ? deg[base + 1] : 0;
    int d2 = (base + 2 < n) ? deg[base + 2] : 0;
    int d3 = (base + 3 < n) ? deg[base + 3] : 0;
    int s = d0 + d1 + d2 + d3;
    sd[t] = s;
#pragma unroll
    for (int off = 1; off < 256; off <<= 1) {
        __syncthreads();
        int v = (t >= off) ? sd[t - off] : 0;
        __syncthreads();
        sd[t] += v;
    }
    __syncthreads();
    int excl = sd[t] - s;
    if (base + 0 < n) scan[base + 0] = excl;
    if (base + 1 < n) scan[base + 1] = excl + d0;
    if (base + 2 < n) scan[base + 2] = excl + d0 + d1;
    if (base + 3 < n) scan[base + 3] = excl + d0 + d1 + d2;
    if (t == 255) part[blockIdx.x] = sd[255];
}

__global__ void k_scan_part(const int* __restrict__ part, int* __restrict__ partscan,
                            int nb) {
    __shared__ int sd[128];
    int t = threadIdx.x;
    int s = (t < nb) ? part[t] : 0;
    sd[t] = s;
#pragma unroll
    for (int off = 1; off < 128; off <<= 1) {
        __syncthreads();
        int v = (t >= off) ? sd[t - off] : 0;
        __syncthreads();
        sd[t] += v;
    }
    __syncthreads();
    if (t < nb) partscan[t] = sd[t] - s;
}

__global__ void k_scan_add(const int* __restrict__ scan, const int* __restrict__ partscan,
                           int* __restrict__ start, int* __restrict__ cursor,
                           int n, int E) {
    int i = blockIdx.x * blockDim.x + threadIdx.x;
    if (i < n) {
        int v = scan[i] + partscan[i >> 10];
        start[i] = v;
        cursor[i] = v;
    }
    if (i == 0) start[n] = E;
}

// ---------------- per-edge weight + direct CSR fill --------------------------
__global__ __launch_bounds__(256) void k_edge_w(const int* __restrict__ edges,
                                                const float* __restrict__ verts,
                                                const float* __restrict__ nacc,
                                                const float* __restrict__ W1,
                                                const float* __restrict__ b1,
                                                const float* __restrict__ W2,
                                                const float* __restrict__ b2,
                                                int* __restrict__ cursor,
                                                int* __restrict__ csr_src,
                                                float* __restrict__ csr_w, int E) {
    __shared__ float sW1[96];
    __shared__ float sb1[32];
    __shared__ float sW2[192];
    __shared__ float sb2[6];
    int tid = threadIdx.x;
    for (int i = tid; i < 96;  i += blockDim.x) sW1[i] = W1[i];
    for (int i = tid; i < 32;  i += blockDim.x) sb1[i] = b1[i];
    for (int i = tid; i < 192; i += blockDim.x) sW2[i] = W2[i];
    for (int i = tid; i < 6;   i += blockDim.x) sb2[i] = b2[i];
    __syncthreads();

    int e = blockIdx.x * blockDim.x + tid;
    if (e >= E) return;
    int src = __ldg(edges + e);
    int dst = __ldg(edges + E + e);

    float dx = __ldg(verts + 3 * dst)     - __ldg(verts + 3 * src);
    float dy = __ldg(verts + 3 * dst + 1) - __ldg(verts + 3 * src + 1);
    float dz = __ldg(verts + 3 * dst + 2) - __ldg(verts + 3 * src + 2);
    float rx = __ldg(nacc + 3 * src), ry = __ldg(nacc + 3 * src + 1), rz = __ldg(nacc + 3 * src + 2);
    float len = sqrtf(rx * rx + ry * ry + rz * rz);
    float inv = 1.0f / (len + 1e-8f);
    float nx = rx * inv, ny = ry * inv, nz = rz * inv;

    float dot = dx * nx + dy * ny + dz * nz;
    float t0 = dx - dot * nx, t1 = dy - dot * ny, t2 = dz - dot * nz;

    float th[6];
#pragma unroll
    for (int m = 0; m < 6; m++) th[m] = sb2[m];
#pragma unroll
    for (int j = 0; j < 32; j++) {
        float h = sb1[j] + t0 * sW1[j] + t1 * sW1[32 + j] + t2 * sW1[64 + j];
        h = fmaxf(h, 0.0f);
#pragma unroll
        for (int m = 0; m < 6; m++) th[m] += h * sW2[j * 6 + m];
    }
    float s0 = th[0] * t0 + th[1] * t1 + th[2] * t2;
    float s1 = th[1] * t0 + th[3] * t1 + th[4] * t2;
    float s2 = th[2] * t0 + th[4] * t1 + th[5] * t2;
    float q = s0 * s0 + s1 * s1 + s2 * s2;
    float wv = expf(-q);

    int pos = atomicAdd(&cursor[dst], 1);
    csr_src[pos] = src;
    csr_w[pos] = wv;
}

// ---------------- gather + fused column stats --------------------------------
__global__ __launch_bounds__(256) void k_gather_stats(const int* __restrict__ start,
                                                      const int* __restrict__ csr_src,
                                                      const float* __restrict__ csr_w,
                                                      const float* __restrict__ x,
                                                      float* __restrict__ p,
                                                      float* __restrict__ stats, int n) {
    int warp = threadIdx.x >> 5, lane = threadIdx.x & 31;
    float4 s1 = make_float4(0.f, 0.f, 0.f, 0.f);
    float4 s2 = make_float4(0.f, 0.f, 0.f, 0.f);

    for (int it = 0; it < 8; it++) {
        int v = blockIdx.x * 64 + it * 8 + warp;
        if (v >= n) break;
        int beg = __ldg(start + v);
        int end = __ldg(start + v + 1);
        float4 acc = make_float4(0.f, 0.f, 0.f, 0.f);
        float dsum = 0.0f;
        int i = beg;
        for (; i + 4 <= end; i += 4) {
            int e0 = __ldg(csr_src + i + 0);
            int e1 = __ldg(csr_src + i + 1);
            int e2 = __ldg(csr_src + i + 2);
            int e3 = __ldg(csr_src + i + 3);
            float w0 = __ldg(csr_w + i + 0);
            float w1 = __ldg(csr_w + i + 1);
            float w2 = __ldg(csr_w + i + 2);
            float w3 = __ldg(csr_w + i + 3);
            float4 a = __ldg((const float4*)(x + (size_t)e0 * C) + lane);
            float4 b = __ldg((const float4*)(x + (size_t)e1 * C) + lane);
            float4 c = __ldg((const float4*)(x + (size_t)e2 * C) + lane);
            float4 d = __ldg((const float4*)(x + (size_t)e3 * C) + lane);
            dsum += (w0 + w1) + (w2 + w3);
            acc.x += w0 * a.x + w1 * b.x + w2 * c.x + w3 * d.x;
            acc.y += w0 * a.y + w1 * b.y + w2 * c.y + w3 * d.y;
            acc.z += w0 * a.z + w1 * b.z + w2 * c.z + w3 * d.z;
            acc.w += w0 * a.w + w1 * b.w + w2 * c.w + w3 * d.w;
        }
        for (; i < end; i++) {
            int s = __ldg(csr_src + i);
            float we = __ldg(csr_w + i);
            float4 xv = __ldg((const float4*)(x + (size_t)s * C) + lane);
            dsum += we;
            acc.x += we * xv.x; acc.y += we * xv.y; acc.z += we * xv.z; acc.w += we * xv.w;
        }
        float rd = 1.0f / (dsum + 1e-5f);
        acc.x *= rd; acc.y *= rd; acc.z *= rd; acc.w *= rd;
        *((float4*)(p + (size_t)v * C) + lane) = acc;
        s1.x += acc.x; s1.y += acc.y; s1.z += acc.z; s1.w += acc.w;
        s2.x += acc.x * acc.x; s2.y += acc.y * acc.y; s2.z += acc.z * acc.z; s2.w += acc.w * acc.w;
    }

    __shared__ float4 red[8][32];
    red[warp][lane] = s1;
    __syncthreads();
    if (threadIdx.x < 128) {
        int col = threadIdx.x;
        float s = 0.0f;
#pragma unroll
        for (int w = 0; w < 8; w++) {
            const float* r = (const float*)&red[w][col >> 2];
            s += r[col & 3];
        }
        atomicAdd(&stats[col], s);
    }
    __syncthreads();
    red[warp][lane] = s2;
    __syncthreads();
    if (threadIdx.x < 128) {
        int col = threadIdx.x;
        float s = 0.0f;
#pragma unroll
        for (int w = 0; w < 8; w++) {
            const float* r = (const float*)&red[w][col >> 2];
            s += r[col & 3];
        }
        atomicAdd(&stats[C + col], s);
    }
}

// ---------------- final: (inline mu/rstd) normalize + ELU, float4 ------------
__global__ __launch_bounds__(256) void k_final(const float* __restrict__ p,
                                               const float* __restrict__ stats,
                                               float* __restrict__ out, int n) {
    __shared__ float smu[C];
    __shared__ float srstd[C];
    int tid = threadIdx.x;
    if (tid < C) {
        float m = stats[tid] / (float)n;
        float var = (stats[C + tid] - (float)n * m * m) / (float)(n - 1);
        var = fmaxf(var, 0.0f);
        smu[tid] = m;
        srstd[tid] = 1.0f / (sqrtf(var) + 1e-5f);
    }
    __syncthreads();
    size_t i4 = (size_t)blockIdx.x * blockDim.x + tid;    // float4 index
    if (i4 >= (size_t)n * 32) return;
    int c4 = (int)(i4 & 31) * 4;
    float4 v = __ldg((const float4*)p + i4);
    float y0 = (v.x - smu[c4 + 0]) * srstd[c4 + 0];
    float y1 = (v.y - smu[c4 + 1]) * srstd[c4 + 1];
    float y2 = (v.z - smu[c4 + 2]) * srstd[c4 + 2];
    float y3 = (v.w - smu[c4 + 3]) * srstd[c4 + 3];
    float4 o;
    o.x = (y0 > 0.0f) ? y0 : expm1f(y0);
    o.y = (y1 > 0.0f) ? y1 : expm1f(y1);
    o.z = (y2 > 0.0f) ? y2 : expm1f(y2);
    o.w = (y3 > 0.0f) ? y3 : expm1f(y3);
    ((float4*)out)[i4] = o;
}

// ---------------- launch -----------------------------------------------------
extern "C" void kernel_launch(void* const* d_in, const int* in_sizes, int n_in,
                              void* d_out, int out_size) {
    const float* features = (const float*)d_in[0];
    const float* vertices = (const float*)d_in[1];
    const int*   edges    = (const int*)d_in[2];
    const int*   faces    = (const int*)d_in[3];
    const float* W1       = (const float*)d_in[4];
    const float* b1       = (const float*)d_in[5];
    const float* W2       = (const float*)d_in[6];
    const float* b2       = (const float*)d_in[7];
    const float* Wlin     = (const float*)d_in[8];
    const float* blin     = (const float*)d_in[9];

    int n = in_sizes[0] / C;
    int e = in_sizes[2] / 2;
    int f = in_sizes[3] / 3;
    if (n > NMAX) n = NMAX;
    if (e > EMAX) e = EMAX;
    if (f > FMAX) f = FMAX;

    float *p_x, *p_p, *p_nacc, *p_stats, *p_csrw;
    int *p_deg, *p_scan, *p_part, *p_partscan, *p_start, *p_cursor, *p_csrsrc;
    uint32_t *p_bh, *p_bl;
    cudaGetSymbolAddress((void**)&p_x, g_x);
    cudaGetSymbolAddress((void**)&p_p, g_p);
    cudaGetSymbolAddress((void**)&p_nacc, g_nacc);
    cudaGetSymbolAddress((void**)&p_stats, g_stats);
    cudaGetSymbolAddress((void**)&p_deg, g_deg);
    cudaGetSymbolAddress((void**)&p_scan, g_scan);
    cudaGetSymbolAddress((void**)&p_part, g_part);
    cudaGetSymbolAddress((void**)&p_partscan, g_partscan);
    cudaGetSymbolAddress((void**)&p_start, g_start);
    cudaGetSymbolAddress((void**)&p_cursor, g_cursor);
    cudaGetSymbolAddress((void**)&p_csrsrc, g_csr_src);
    cudaGetSymbolAddress((void**)&p_csrw, g_csr_w);
    cudaGetSymbolAddress((void**)&p_bh, g_Bh);
    cudaGetSymbolAddress((void**)&p_bl, g_Bl);

    float* out = (float*)d_out;

    const int GEMM_SMEM = 2 * 64 * BPITCH * 4;    // 34816 bytes
    cudaFuncSetAttribute(k_gemm_mma, cudaFuncAttributeMaxDynamicSharedMemorySize, GEMM_SMEM);

    int nb = (n + 1023) / 1024;                   // scan blocks (<=128)
    dim3 ggrid((n + 127) / 128, 2);

    k_prepB<<<32, 256>>>(Wlin, p_bh, p_bl);                                        // 0
    k_zero_misc<<<(n * 3 + 255) / 256, 256>>>(p_nacc, p_deg, p_stats, n);          // 1
    k_face_count<<<(f + e + 255) / 256, 256>>>(faces, vertices, edges, p_nacc,
                                               p_deg, f, e);                       // 2
    k_gemm_mma<<<ggrid, 256, GEMM_SMEM>>>(features, p_bh, p_bl, blin, p_x, n);     // 3 (ncu)
    k_scan_block<<<nb, 256>>>(p_deg, p_scan, p_part, n);                           // 4
    k_scan_part<<<1, 128>>>(p_part, p_partscan, nb);                               // 5
    k_scan_add<<<(n + 255) / 256, 256>>>(p_scan, p_partscan, p_start, p_cursor, n, e); // 6
    k_edge_w<<<(e + 255) / 256, 256>>>(edges, vertices, p_nacc, W1, b1, W2, b2,
                                       p_cursor, p_csrsrc, p_csrw, e);             // 7
    k_gather_stats<<<(n + 63) / 64, 256>>>(p_start, p_csrsrc, p_csrw, p_x, p_p,
                                           p_stats, n);                            // 8
    k_final<<<(n * 32 + 255) / 256, 256>>>(p_p, p_stats, out, n);                  // 9
}

// round 14
// speedup vs baseline: 1.5081x; 1.0679x over previous
#include <cuda_runtime.h>
#include <cuda_bf16.h>
#include <cstdint>
#include <cstddef>

#define NMAX 100000
#define EMAX 600000
#define FMAX 200000
#define C    128

// ---------------- scratch (static device globals; no runtime alloc) ----------
__device__ float g_x[(size_t)NMAX * C];      // features @ Wlin + blin
__device__ float g_p[(size_t)NMAX * C];      // aggregated & den-normalized rows
__device__ float g_nacc[NMAX * 3];           // accumulated face normals (raw)
__device__ float g_stats[256];               // colsum[128], colsum2[128]
// CSR-by-dst
__device__ int   g_deg[NMAX];
__device__ int   g_scan[NMAX];               // in-block exclusive scan
__device__ int   g_part[128];                // block partial sums
__device__ int   g_start[NMAX + 1];
__device__ int   g_cursor[NMAX];
__device__ int   g_csr_src[EMAX];
__device__ float g_csr_w[EMAX];
// pre-converted W bf16 hi/lo, layout [n][paired-k] pitch 72 u32:
// for kp (k-pair 0..63): ch=kp>>3, tg=kp&3, s=(kp>>2)&1 -> off = ch*8 + tg*2 + s
// so the two fragment words (kp, kp+4) sit adjacent -> LDS.64, conflict-free.
#define BPITCH 72
__device__ uint32_t g_Bh[128 * BPITCH];
__device__ uint32_t g_Bl[128 * BPITCH];

// ---------------- init: zero accumulators + prep B (fused) -------------------
__global__ void k_init(float* __restrict__ nacc, int* __restrict__ deg,
                       float* __restrict__ stats, const float* __restrict__ W,
                       uint32_t* __restrict__ bh, uint32_t* __restrict__ bl,
                       int n, int zeroBlocks) {
    if ((int)blockIdx.x < zeroBlocks) {
        int i = blockIdx.x * 256 + threadIdx.x;
        if (i < n * 3) nacc[i] = 0.0f;
        if (i < n) deg[i] = 0;
        if (i < 256) stats[i] = 0.0f;
    } else {
        int idx = (blockIdx.x - zeroBlocks) * 256 + threadIdx.x;   // 128*64
        if (idx >= 128 * 64) return;
        int c = idx >> 6, kp = idx & 63;
        float v0 = __ldg(W + (size_t)(2 * kp) * C + c);
        float v1 = __ldg(W + (size_t)(2 * kp + 1) * C + c);
        __nv_bfloat16 h0 = __float2bfloat16_rn(v0);
        __nv_bfloat16 h1 = __float2bfloat16_rn(v1);
        __nv_bfloat16 l0 = __float2bfloat16_rn(v0 - __bfloat162float(h0));
        __nv_bfloat16 l1 = __float2bfloat16_rn(v1 - __bfloat162float(h1));
        __nv_bfloat162 H(h0, h1), L(l0, l1);
        int off = (kp >> 3) * 8 + (kp & 3) * 2 + ((kp >> 2) & 1);
        bh[c * BPITCH + off] = *(uint32_t*)&H;
        bl[c * BPITCH + off] = *(uint32_t*)&L;
    }
}

// ---------------- mma.sync helpers -------------------------------------------
__device__ __forceinline__ void mma16816(float* c, const uint32_t* a,
                                         uint32_t b0, uint32_t b1) {
    asm volatile(
        "mma.sync.aligned.m16n8k16.row.col.f32.bf16.bf16.f32 "
        "{%0,%1,%2,%3}, {%4,%5,%6,%7}, {%8,%9}, {%0,%1,%2,%3};"
        : "+f"(c[0]), "+f"(c[1]), "+f"(c[2]), "+f"(c[3])
        : "r"(a[0]), "r"(a[1]), "r"(a[2]), "r"(a[3]), "r"(b0), "r"(b1));
}

__device__ __forceinline__ void cvt2(float2 v, uint32_t& hi, uint32_t& lo) {
    __nv_bfloat16 h0 = __float2bfloat16_rn(v.x);
    __nv_bfloat16 h1 = __float2bfloat16_rn(v.y);
    __nv_bfloat16 l0 = __float2bfloat16_rn(v.x - __bfloat162float(h0));
    __nv_bfloat16 l1 = __float2bfloat16_rn(v.y - __bfloat162float(h1));
    __nv_bfloat162 H(h0, h1), L(l0, l1);
    hi = *(uint32_t*)&H;
    lo = *(uint32_t*)&L;
}

// ---------------- fused: bf16x3 mma GEMM + face normals + degree count -------
// Blocks [0, gemmBlocks): GEMM. Warp tile 16 rows x 64 cols; CTA = 128 rows x
// one n-half (gid&1). B-half staged in smem (36.9KB), paired-k layout ->
// LDS.64 fragment loads. launch_bounds(256,3) -> 3 CTAs/SM.
// Blocks [gemmBlocks, ...): face-normal scatter + dst degree count (no smem).
extern __shared__ uint32_t sB[];   // [2][64*BPITCH] hi then lo

__global__ __launch_bounds__(256, 3) void k_gemm_face(
    const float* __restrict__ feat, const uint32_t* __restrict__ gBh,
    const uint32_t* __restrict__ gBl, const float* __restrict__ bias,
    float* __restrict__ xout,
    const int* __restrict__ faces, const float* __restrict__ verts,
    const int* __restrict__ edges, float* __restrict__ nacc,
    int* __restrict__ deg,
    int n, int F, int E, int gemmBlocks) {
    int tid = threadIdx.x;
    if ((int)blockIdx.x >= gemmBlocks) {
        // ---- face normals + degree count branch ----
        int t = (blockIdx.x - gemmBlocks) * 256 + tid;
        if (t < F) {
            int f = t;
            int i0 = __ldg(faces + f);
            int i1 = __ldg(faces + F + f);
            int i2 = __ldg(faces + 2 * F + f);
            float v0x = __ldg(verts + 3 * i0), v0y = __ldg(verts + 3 * i0 + 1), v0z = __ldg(verts + 3 * i0 + 2);
            float v1x = __ldg(verts + 3 * i1), v1y = __ldg(verts + 3 * i1 + 1), v1z = __ldg(verts + 3 * i1 + 2);
            float v2x = __ldg(verts + 3 * i2), v2y = __ldg(verts + 3 * i2 + 1), v2z = __ldg(verts + 3 * i2 + 2);
            float ax = v1x - v0x, ay = v1y - v0y, az = v1z - v0z;
            float bx = v2x - v0x, by = v2y - v0y, bz = v2z - v0z;
            float nx = ay * bz - az * by;
            float ny = az * bx - ax * bz;
            float nz = ax * by - ay * bx;
            atomicAdd(&nacc[3 * i0 + 0], nx); atomicAdd(&nacc[3 * i0 + 1], ny); atomicAdd(&nacc[3 * i0 + 2], nz);
            atomicAdd(&nacc[3 * i1 + 0], nx); atomicAdd(&nacc[3 * i1 + 1], ny); atomicAdd(&nacc[3 * i1 + 2], nz);
            atomicAdd(&nacc[3 * i2 + 0], nx); atomicAdd(&nacc[3 * i2 + 1], ny); atomicAdd(&nacc[3 * i2 + 2], nz);
        } else {
            int e = t - F;
            if (e < E) atomicAdd(&deg[__ldg(edges + E + e)], 1);
        }
        return;
    }

    // ---- GEMM branch ----
    const int BSZ = 64 * BPITCH;           // 4608 u32 = 18432 B per matrix
    int bx = blockIdx.x >> 1;
    int nh = blockIdx.x & 1;               // n-half
    {
        const float4* s1 = (const float4*)(gBh + nh * BSZ);
        const float4* s2 = (const float4*)(gBl + nh * BSZ);
        float4* d1 = (float4*)sB;
        float4* d2 = (float4*)(sB + BSZ);
        for (int i = tid; i < BSZ / 4; i += 256) { d1[i] = __ldg(s1 + i); d2[i] = __ldg(s2 + i); }
    }
    __syncthreads();

    int warp = tid >> 5, lane = tid & 31;
    int gid = lane >> 2, tg = lane & 3;
    int r0 = bx * 128 + warp * 16 + gid;
    int r1 = r0 + 8;
    int r0c = (r0 < n) ? r0 : (n - 1);
    int r1c = (r1 < n) ? r1 : (n - 1);
    const float* A0 = feat + (size_t)r0c * C;
    const float* A1 = feat + (size_t)r1c * C;

    float acc[8][4];
#pragma unroll
    for (int t = 0; t < 8; t++) { acc[t][0] = acc[t][1] = acc[t][2] = acc[t][3] = 0.0f; }

    const uint32_t* Bh = sB;
    const uint32_t* Bl = sB + BSZ;

#pragma unroll
    for (int ch = 0; ch < 8; ch++) {
        int k0 = ch * 16 + tg * 2;
        float2 p00 = __ldg((const float2*)(A0 + k0));
        float2 p10 = __ldg((const float2*)(A1 + k0));
        float2 p01 = __ldg((const float2*)(A0 + k0 + 8));
        float2 p11 = __ldg((const float2*)(A1 + k0 + 8));
        uint32_t ah[4], al[4];
        cvt2(p00, ah[0], al[0]);
        cvt2(p10, ah[1], al[1]);
        cvt2(p01, ah[2], al[2]);
        cvt2(p11, ah[3], al[3]);
        int bbase = ch * 8 + tg * 2;
#pragma unroll
        for (int t = 0; t < 8; t++) {
            int ci = (t * 8 + gid) * BPITCH + bbase;     // local n-row within half
            uint2 bh2 = *(const uint2*)(Bh + ci);
            uint2 bl2 = *(const uint2*)(Bl + ci);
            mma16816(acc[t], ah, bh2.x, bh2.y);
            mma16816(acc[t], ah, bl2.x, bl2.y);
            mma16816(acc[t], al, bh2.x, bh2.y);
        }
    }

    // epilogue: +bias, float2 stores into this CTA's n-half
#pragma unroll
    for (int t = 0; t < 8; t++) {
        int c0 = nh * 64 + t * 8 + tg * 2;
        float2 bv = __ldg((const float2*)(bias + c0));
        if (r0 < n) {
            float2 o = make_float2(acc[t][0] + bv.x, acc[t][1] + bv.y);
            *(float2*)(xout + (size_t)r0 * C + c0) = o;
        }
        if (r1 < n) {
            float2 o = make_float2(acc[t][2] + bv.x, acc[t][3] + bv.y);
            *(float2*)(xout + (size_t)r1 * C + c0) = o;
        }
    }
}

// ---------------- exclusive scan over deg: block pass ------------------------
__global__ __launch_bounds__(256) void k_scan_block(const int* __restrict__ deg,
                                                    int* __restrict__ scan,
                                                    int* __restrict__ part, int n) {
    __shared__ int sd[256];
    int t = threadIdx.x;
    int base = blockIdx.x * 1024 + t * 4;
    int d0 = (base + 0 < n) ? deg[base + 0] : 0;
    int d1 = (base + 1 < n) ? deg[base + 1] : 0;
    int d2 = (base + 2 < n) ? deg[base + 2] : 0;
    int d3 = (base + 3 < n) ? deg[base + 3] : 0;
    int s = d0 + d1 + d2 + d3;
    sd[t] = s;
#pragma unroll
    for (int off = 1; off < 256; off <<= 1) {
        __syncthreads();
        int v = (t >= off) ? sd[t - off] : 0;
        __syncthreads();
        sd[t] += v;
    }
    __syncthreads();
    int excl = sd[t] - s;
    if (base + 0 < n) scan[base + 0] = excl;
    if (base + 1 < n) scan[base + 1] = excl + d0;
    if (base + 2 < n) scan[base + 2] = excl + d0 + d1;
    if (base + 3 < n) scan[base + 3] = excl + d0 + d1 + d2;
    if (t == 255) part[blockIdx.x] = sd[255];
}

// ---------------- scan fixup: inline partial-scan + add-back -----------------
__global__ __launch_bounds__(256) void k_scan_add(const int* __restrict__ scan,
                                                  const int* __restrict__ part,
                                                  int* __restrict__ start,
                                                  int* __restrict__ cursor,
                                                  int n, int E, int nb) {
    __shared__ int sp[128];
    __shared__ int so[128];
    int t = threadIdx.x;
    if (t < 128) {
        int s = (t < nb) ? __ldg(part + t) : 0;
        sp[t] = s;
        so[t] = s;
    }
    __syncthreads();
#pragma unroll
    for (int off = 1; off < 128; off <<= 1) {
        int v = 0;
        if (t < 128 && t >= off) v = sp[t - off];
        __syncthreads();
        if (t < 128) sp[t] += v;
        __syncthreads();
    }
    int i = blockIdx.x * 256 + t;
    if (i < n) {
        int b = i >> 10;
        int v = scan[i] + sp[b] - so[b];     // + exclusive prefix of partials
        start[i] = v;
        cursor[i] = v;
    }
    if (i == 0) start[n] = E;
}

// ---------------- per-edge weight + direct CSR fill --------------------------
__global__ __launch_bounds__(256) void k_edge_w(const int* __restrict__ edges,
                                                const float* __restrict__ verts,
                                                const float* __restrict__ nacc,
                                                const float* __restrict__ W1,
                                                const float* __restrict__ b1,
                                                const float* __restrict__ W2,
                                                const float* __restrict__ b2,
                                                int* __restrict__ cursor,
                                                int* __restrict__ csr_src,
                                                float* __restrict__ csr_w, int E) {
    __shared__ float sW1[96];
    __shared__ float sb1[32];
    __shared__ float sW2[192];
    __shared__ float sb2[6];
    int tid = threadIdx.x;
    for (int i = tid; i < 96;  i += blockDim.x) sW1[i] = W1[i];
    for (int i = tid; i < 32;  i += blockDim.x) sb1[i] = b1[i];
    for (int i = tid; i < 192; i += blockDim.x) sW2[i] = W2[i];
    for (int i = tid; i < 6;   i += blockDim.x) sb2[i] = b2[i];
    __syncthreads();

    int e = blockIdx.x * blockDim.x + tid;
    if (e >= E) return;
    int src = __ldg(edges + e);
    int dst = __ldg(edges + E + e);

    float dx = __ldg(verts + 3 * dst)     - __ldg(verts + 3 * src);
    float dy = __ldg(verts + 3 * dst + 1) - __ldg(verts + 3 * src + 1);
    float dz = __ldg(verts + 3 * dst + 2) - __ldg(verts + 3 * src + 2);
    float rx = __ldg(nacc + 3 * src), ry = __ldg(nacc + 3 * src + 1), rz = __ldg(nacc + 3 * src + 2);
    float len = sqrtf(rx * rx + ry * ry + rz * rz);
    float inv = 1.0f / (len + 1e-8f);
    float nx = rx * inv, ny = ry * inv, nz = rz * inv;

    float dot = dx * nx + dy * ny + dz * nz;
    float t0 = dx - dot * nx, t1 = dy - dot * ny, t2 = dz - dot * nz;

    float th[6];
#pragma unroll
    for (int m = 0; m < 6; m++) th[m] = sb2[m];
#pragma unroll
    for (int j = 0; j < 32; j++) {
        float h = sb1[j] + t0 * sW1[j] + t1 * sW1[32 + j] + t2 * sW1[64 + j];
        h = fmaxf(h, 0.0f);
#pragma unroll
        for (int m = 0; m < 6; m++) th[m] += h * sW2[j * 6 + m];
    }
    float s0 = th[0] * t0 + th[1] * t1 + th[2] * t2;
    float s1 = th[1] * t0 + th[3] * t1 + th[4] * t2;
    float s2 = th[2] * t0 + th[4] * t1 + th[5] * t2;
    float q = s0 * s0 + s1 * s1 + s2 * s2;
    float wv = expf(-q);

    int pos = atomicAdd(&cursor[dst], 1);
    csr_src[pos] = src;
    csr_w[pos] = wv;
}

// ---------------- gather + fused column stats --------------------------------
__global__ __launch_bounds__(256) void k_gather_stats(const int* __restrict__ start,
                                                      const int* __restrict__ csr_src,
                                                      const float* __restrict__ csr_w,
                                                      const float* __restrict__ x,
                                                      float* __restrict__ p,
                                                      float* __restrict__ stats, int n) {
    int warp = threadIdx.x >> 5, lane = threadIdx.x & 31;
    float4 s1 = make_float4(0.f, 0.f, 0.f, 0.f);
    float4 s2 = make_float4(0.f, 0.f, 0.f, 0.f);

    for (int it = 0; it < 8; it++) {
        int v = blockIdx.x * 64 + it * 8 + warp;
        if (v >= n) break;
        int beg = __ldg(start + v);
        int end = __ldg(start + v + 1);
        float4 acc = make_float4(0.f, 0.f, 0.f, 0.f);
        float dsum = 0.0f;
        int i = beg;
        for (; i + 4 <= end; i += 4) {
            int e0 = __ldg(csr_src + i + 0);
            int e1 = __ldg(csr_src + i + 1);
            int e2 = __ldg(csr_src + i + 2);
            int e3 = __ldg(csr_src + i + 3);
            float w0 = __ldg(csr_w + i + 0);
            float w1 = __ldg(csr_w + i + 1);
            float w2 = __ldg(csr_w + i + 2);
            float w3 = __ldg(csr_w + i + 3);
            float4 a = __ldg((const float4*)(x + (size_t)e0 * C) + lane);
            float4 b = __ldg((const float4*)(x + (size_t)e1 * C) + lane);
            float4 c = __ldg((const float4*)(x + (size_t)e2 * C) + lane);
            float4 d = __ldg((const float4*)(x + (size_t)e3 * C) + lane);
            dsum += (w0 + w1) + (w2 + w3);
            acc.x += w0 * a.x + w1 * b.x + w2 * c.x + w3 * d.x;
            acc.y += w0 * a.y + w1 * b.y + w2 * c.y + w3 * d.y;
            acc.z += w0 * a.z + w1 * b.z + w2 * c.z + w3 * d.z;
            acc.w += w0 * a.w + w1 * b.w + w2 * c.w + w3 * d.w;
        }
        for (; i < end; i++) {
            int s = __ldg(csr_src + i);
            float we = __ldg(csr_w + i);
            float4 xv = __ldg((const float4*)(x + (size_t)s * C) + lane);
            dsum += we;
            acc.x += we * xv.x; acc.y += we * xv.y; acc.z += we * xv.z; acc.w += we * xv.w;
        }
        float rd = 1.0f / (dsum + 1e-5f);
        acc.x *= rd; acc.y *= rd; acc.z *= rd; acc.w *= rd;
        *((float4*)(p + (size_t)v * C) + lane) = acc;
        s1.x += acc.x; s1.y += acc.y; s1.z += acc.z; s1.w += acc.w;
        s2.x += acc.x * acc.x; s2.y += acc.y * acc.y; s2.z += acc.z * acc.z; s2.w += acc.w * acc.w;
    }

    __shared__ float4 red[8][32];
    red[warp][lane] = s1;
    __syncthreads();
    if (threadIdx.x < 128) {
        int col = threadIdx.x;
        float s = 0.0f;
#pragma unroll
        for (int w = 0; w < 8; w++) {
            const float* r = (const float*)&red[w][col >> 2];
            s += r[col & 3];
        }
        atomicAdd(&stats[col], s);
    }
    __syncthreads();
    red[warp][lane] = s2;
    __syncthreads();
    if (threadIdx.x < 128) {
        int col = threadIdx.x;
        float s = 0.0f;
#pragma unroll
        for (int w = 0; w < 8; w++) {
            const float* r = (const float*)&red[w][col >> 2];
            s += r[col & 3];
        }
        atomicAdd(&stats[C + col], s);
    }
}

// ---------------- final: (inline mu/rstd) normalize + ELU, float4 ------------
__global__ __launch_bounds__(256) void k_final(const float* __restrict__ p,
                                               const float* __restrict__ stats,
                                               float* __restrict__ out, int n) {
    __shared__ float smu[C];
    __shared__ float srstd[C];
    int tid = threadIdx.x;
    if (tid < C) {
        float m = stats[tid] / (float)n;
        float var = (stats[C + tid] - (float)n * m * m) / (float)(n - 1);
        var = fmaxf(var, 0.0f);
        smu[tid] = m;
        srstd[tid] = 1.0f / (sqrtf(var) + 1e-5f);
    }
    __syncthreads();
    size_t i4 = (size_t)blockIdx.x * blockDim.x + tid;    // float4 index
    if (i4 >= (size_t)n * 32) return;
    int c4 = (int)(i4 & 31) * 4;
    float4 v = __ldg((const float4*)p + i4);
    float y0 = (v.x - smu[c4 + 0]) * srstd[c4 + 0];
    float y1 = (v.y - smu[c4 + 1]) * srstd[c4 + 1];
    float y2 = (v.z - smu[c4 + 2]) * srstd[c4 + 2];
    float y3 = (v.w - smu[c4 + 3]) * srstd[c4 + 3];
    float4 o;
    o.x = (y0 > 0.0f) ? y0 : expm1f(y0);
    o.y = (y1 > 0.0f) ? y1 : expm1f(y1);
    o.z = (y2 > 0.0f) ? y2 : expm1f(y2);
    o.w = (y3 > 0.0f) ? y3 : expm1f(y3);
    ((float4*)out)[i4] = o;
}

// ---------------- launch -----------------------------------------------------
extern "C" void kernel_launch(void* const* d_in, const int* in_sizes, int n_in,
                              void* d_out, int out_size) {
    const float* features = (const float*)d_in[0];
    const float* vertices = (const float*)d_in[1];
    const int*   edges    = (const int*)d_in[2];
    const int*   faces    = (const int*)d_in[3];
    const float* W1       = (const float*)d_in[4];
    const float* b1       = (const float*)d_in[5];
    const float* W2       = (const float*)d_in[6];
    const float* b2       = (const float*)d_in[7];
    const float* Wlin     = (const float*)d_in[8];
    const float* blin     = (const float*)d_in[9];

    int n = in_sizes[0] / C;
    int e = in_sizes[2] / 2;
    int f = in_sizes[3] / 3;
    if (n > NMAX) n = NMAX;
    if (e > EMAX) e = EMAX;
    if (f > FMAX) f = FMAX;

    float *p_x, *p_p, *p_nacc, *p_stats, *p_csrw;
    int *p_deg, *p_scan, *p_part, *p_start, *p_cursor, *p_csrsrc;
    uint32_t *p_bh, *p_bl;
    cudaGetSymbolAddress((void**)&p_x, g_x);
    cudaGetSymbolAddress((void**)&p_p, g_p);
    cudaGetSymbolAddress((void**)&p_nacc, g_nacc);
    cudaGetSymbolAddress((void**)&p_stats, g_stats);
    cudaGetSymbolAddress((void**)&p_deg, g_deg);
    cudaGetSymbolAddress((void**)&p_scan, g_scan);
    cudaGetSymbolAddress((void**)&p_part, g_part);
    cudaGetSymbolAddress((void**)&p_start, g_start);
    cudaGetSymbolAddress((void**)&p_cursor, g_cursor);
    cudaGetSymbolAddress((void**)&p_csrsrc, g_csr_src);
    cudaGetSymbolAddress((void**)&p_csrw, g_csr_w);
    cudaGetSymbolAddress((void**)&p_bh, g_Bh);
    cudaGetSymbolAddress((void**)&p_bl, g_Bl);

    float* out = (float*)d_out;

    const int GEMM_SMEM = 2 * 64 * BPITCH * 4;    // 36864 bytes
    cudaFuncSetAttribute(k_gemm_face, cudaFuncAttributeMaxDynamicSharedMemorySize, GEMM_SMEM);

    int zeroBlocks = (n * 3 + 255) / 256;
    int gemmBlocks = ((n + 127) / 128) * 2;
    int faceBlocks = (f + e + 255) / 256;
    int nb = (n + 1023) / 1024;                   // scan blocks (<=128)

    k_init<<<zeroBlocks + 32, 256>>>(p_nacc, p_deg, p_stats, Wlin, p_bh, p_bl,
                                     n, zeroBlocks);                               // 0
    k_gemm_face<<<gemmBlocks + faceBlocks, 256, GEMM_SMEM>>>(
        features, p_bh, p_bl, blin, p_x,
        faces, vertices, edges, p_nacc, p_deg,
        n, f, e, gemmBlocks);                                                      // 1
    k_scan_block<<<nb, 256>>>(p_deg, p_scan, p_part, n);                           // 2
    k_scan_add<<<(n + 255) / 256, 256>>>(p_scan, p_part, p_start, p_cursor,
                                         n, e, nb);                                // 3 (ncu)
    k_edge_w<<<(e + 255) / 256, 256>>>(edges, vertices, p_nacc, W1, b1, W2, b2,
                                       p_cursor, p_csrsrc, p_csrw, e);             // 4
    k_gather_stats<<<(n + 63) / 64, 256>>>(p_start, p_csrsrc, p_csrw, p_x, p_p,
                                           p_stats, n);                            // 5
    k_final<<<(n * 32 + 255) / 256, 256>>>(p_p, p_stats, out, n);                  // 6
}

// round 16
// speedup vs baseline: 1.6030x; 1.0630x over previous
#include <cuda_runtime.h>
#include <cuda_bf16.h>
#include <cstdint>
#include <cstddef>

#define NMAX 100000
#define EMAX 600000
#define FMAX 200000
#define C    128

// ---------------- scratch (static device globals; no runtime alloc) ----------
__device__ float g_x[(size_t)NMAX * C];      // features @ Wlin + blin
__device__ float g_p[(size_t)NMAX * C];      // aggregated & den-normalized rows
__device__ float4 g_nacc4[NMAX];             // accumulated face normals (xyz, pad)
__device__ float4 g_verts4[NMAX];            // repacked vertices (xyz, 0)
__device__ float g_stats[256];               // colsum[128], colsum2[128]
// CSR-by-dst
__device__ int   g_deg[NMAX];
__device__ int   g_scan[NMAX];               // in-block exclusive scan
__device__ int   g_part[128];                // block partial sums
__device__ int   g_start[NMAX + 1];
__device__ int   g_cursor[NMAX];
__device__ int   g_csr_src[EMAX];
__device__ float g_csr_w[EMAX];
// pre-converted W bf16 hi/lo, layout [n][paired-k] pitch 72 u32 (LDS.64 pairs)
#define BPITCH 72
__device__ uint32_t g_Bh[128 * BPITCH];
__device__ uint32_t g_Bl[128 * BPITCH];

// ---------------- init: zero + vertex repack + prep B (fused) ----------------
__global__ void k_init(const float* __restrict__ verts, float4* __restrict__ verts4,
                       float4* __restrict__ nacc4, int* __restrict__ deg,
                       float* __restrict__ stats,
                       const float* __restrict__ W,
                       uint32_t* __restrict__ bh, uint32_t* __restrict__ bl,
                       int n, int mainBlocks) {
    if ((int)blockIdx.x < mainBlocks) {
        int i = blockIdx.x * 256 + threadIdx.x;
        if (i < n) {
            verts4[i] = make_float4(__ldg(verts + 3 * i), __ldg(verts + 3 * i + 1),
                                    __ldg(verts + 3 * i + 2), 0.0f);
            nacc4[i] = make_float4(0.f, 0.f, 0.f, 0.f);
            deg[i] = 0;
        }
        if (i < 256) stats[i] = 0.0f;
    } else {
        int idx = (blockIdx.x - mainBlocks) * 256 + threadIdx.x;   // 128*64
        if (idx >= 128 * 64) return;
        int c = idx >> 6, kp = idx & 63;
        float v0 = __ldg(W + (size_t)(2 * kp) * C + c);
        float v1 = __ldg(W + (size_t)(2 * kp + 1) * C + c);
        __nv_bfloat16 h0 = __float2bfloat16_rn(v0);
        __nv_bfloat16 h1 = __float2bfloat16_rn(v1);
        __nv_bfloat16 l0 = __float2bfloat16_rn(v0 - __bfloat162float(h0));
        __nv_bfloat16 l1 = __float2bfloat16_rn(v1 - __bfloat162float(h1));
        __nv_bfloat162 H(h0, h1), L(l0, l1);
        int off = (kp >> 3) * 8 + (kp & 3) * 2 + ((kp >> 2) & 1);
        bh[c * BPITCH + off] = *(uint32_t*)&H;
        bl[c * BPITCH + off] = *(uint32_t*)&L;
    }
}

// ---------------- mma.sync helpers -------------------------------------------
__device__ __forceinline__ void mma16816(float* c, const uint32_t* a,
                                         uint32_t b0, uint32_t b1) {
    asm volatile(
        "mma.sync.aligned.m16n8k16.row.col.f32.bf16.bf16.f32 "
        "{%0,%1,%2,%3}, {%4,%5,%6,%7}, {%8,%9}, {%0,%1,%2,%3};"
        : "+f"(c[0]), "+f"(c[1]), "+f"(c[2]), "+f"(c[3])
        : "r"(a[0]), "r"(a[1]), "r"(a[2]), "r"(a[3]), "r"(b0), "r"(b1));
}

__device__ __forceinline__ void cvt2(float2 v, uint32_t& hi, uint32_t& lo) {
    __nv_bfloat16 h0 = __float2bfloat16_rn(v.x);
    __nv_bfloat16 h1 = __float2bfloat16_rn(v.y);
    __nv_bfloat16 l0 = __float2bfloat16_rn(v.x - __bfloat162float(h0));
    __nv_bfloat16 l1 = __float2bfloat16_rn(v.y - __bfloat162float(h1));
    __nv_bfloat162 H(h0, h1), L(l0, l1);
    hi = *(uint32_t*)&H;
    lo = *(uint32_t*)&L;
}

__device__ __forceinline__ void red_add_v4(float4* p, float x, float y, float z) {
    asm volatile("red.global.add.v4.f32 [%0], {%1, %2, %3, %4};"
                 :: "l"(p), "f"(x), "f"(y), "f"(z), "f"(0.0f) : "memory");
}

// ---------------- fused: bf16x3 mma GEMM + face normals + degree count -------
extern __shared__ uint32_t sB[];   // [2][64*BPITCH] hi then lo

__global__ __launch_bounds__(256, 3) void k_gemm_face(
    const float* __restrict__ feat, const uint32_t* __restrict__ gBh,
    const uint32_t* __restrict__ gBl, const float* __restrict__ bias,
    float* __restrict__ xout,
    const int* __restrict__ faces, const float4* __restrict__ verts4,
    const int* __restrict__ edges, float4* __restrict__ nacc4,
    int* __restrict__ deg,
    int n, int F, int E, int gemmBlocks) {
    int tid = threadIdx.x;
    if ((int)blockIdx.x >= gemmBlocks) {
        // ---- face normals (v4 RED) + degree count branch ----
        int t = (blockIdx.x - gemmBlocks) * 256 + tid;
        if (t < F) {
            int f = t;
            int i0 = __ldg(faces + f);
            int i1 = __ldg(faces + F + f);
            int i2 = __ldg(faces + 2 * F + f);
            float4 v0 = __ldg(verts4 + i0);
            float4 v1 = __ldg(verts4 + i1);
            float4 v2 = __ldg(verts4 + i2);
            float ax = v1.x - v0.x, ay = v1.y - v0.y, az = v1.z - v0.z;
            float bx = v2.x - v0.x, by = v2.y - v0.y, bz = v2.z - v0.z;
            float nx = ay * bz - az * by;
            float ny = az * bx - ax * bz;
            float nz = ax * by - ay * bx;
            red_add_v4(nacc4 + i0, nx, ny, nz);
            red_add_v4(nacc4 + i1, nx, ny, nz);
            red_add_v4(nacc4 + i2, nx, ny, nz);
        } else {
            int e = t - F;
            if (e < E) atomicAdd(&deg[__ldg(edges + E + e)], 1);
        }
        return;
    }

    // ---- GEMM branch (proven round-13/14 core) ----
    const int BSZ = 64 * BPITCH;           // 4608 u32 = 18432 B per matrix
    int bx = blockIdx.x >> 1;
    int nh = blockIdx.x & 1;               // n-half
    {
        const float4* s1 = (const float4*)(gBh + nh * BSZ);
        const float4* s2 = (const float4*)(gBl + nh * BSZ);
        float4* d1 = (float4*)sB;
        float4* d2 = (float4*)(sB + BSZ);
        for (int i = tid; i < BSZ / 4; i += 256) { d1[i] = __ldg(s1 + i); d2[i] = __ldg(s2 + i); }
    }
    __syncthreads();

    int warp = tid >> 5, lane = tid & 31;
    int gid = lane >> 2, tg = lane & 3;
    int r0 = bx * 128 + warp * 16 + gid;
    int r1 = r0 + 8;
    int r0c = (r0 < n) ? r0 : (n - 1);
    int r1c = (r1 < n) ? r1 : (n - 1);
    const float* A0 = feat + (size_t)r0c * C;
    const float* A1 = feat + (size_t)r1c * C;

    float acc[8][4];
#pragma unroll
    for (int t = 0; t < 8; t++) { acc[t][0] = acc[t][1] = acc[t][2] = acc[t][3] = 0.0f; }

    const uint32_t* Bh = sB;
    const uint32_t* Bl = sB + BSZ;

#pragma unroll
    for (int ch = 0; ch < 8; ch++) {
        int k0 = ch * 16 + tg * 2;
        float2 p00 = __ldg((const float2*)(A0 + k0));
        float2 p10 = __ldg((const float2*)(A1 + k0));
        float2 p01 = __ldg((const float2*)(A0 + k0 + 8));
        float2 p11 = __ldg((const float2*)(A1 + k0 + 8));
        uint32_t ah[4], al[4];
        cvt2(p00, ah[0], al[0]);
        cvt2(p10, ah[1], al[1]);
        cvt2(p01, ah[2], al[2]);
        cvt2(p11, ah[3], al[3]);
        int bbase = ch * 8 + tg * 2;
#pragma unroll
        for (int t = 0; t < 8; t++) {
            int ci = (t * 8 + gid) * BPITCH + bbase;
            uint2 bh2 = *(const uint2*)(Bh + ci);
            uint2 bl2 = *(const uint2*)(Bl + ci);
            mma16816(acc[t], ah, bh2.x, bh2.y);
            mma16816(acc[t], ah, bl2.x, bl2.y);
            mma16816(acc[t], al, bh2.x, bh2.y);
        }
    }

#pragma unroll
    for (int t = 0; t < 8; t++) {
        int c0 = nh * 64 + t * 8 + tg * 2;
        float2 bv = __ldg((const float2*)(bias + c0));
        if (r0 < n) {
            float2 o = make_float2(acc[t][0] + bv.x, acc[t][1] + bv.y);
            *(float2*)(xout + (size_t)r0 * C + c0) = o;
        }
        if (r1 < n) {
            float2 o = make_float2(acc[t][2] + bv.x, acc[t][3] + bv.y);
            *(float2*)(xout + (size_t)r1 * C + c0) = o;
        }
    }
}

// ---------------- exclusive scan over deg: block pass ------------------------
__global__ __launch_bounds__(256) void k_scan_block(const int* __restrict__ deg,
                                                    int* __restrict__ scan,
                                                    int* __restrict__ part, int n) {
    __shared__ int sd[256];
    int t = threadIdx.x;
    int base = blockIdx.x * 1024 + t * 4;
    int d0 = (base + 0 < n) ? deg[base + 0] : 0;
    int d1 = (base + 1 < n) ? deg[base + 1] : 0;
    int d2 = (base + 2 < n) ? deg[base + 2] : 0;
    int d3 = (base + 3 < n) ? deg[base + 3] : 0;
    int s = d0 + d1 + d2 + d3;
    sd[t] = s;
#pragma unroll
    for (int off = 1; off < 256; off <<= 1) {
        __syncthreads();
        int v = (t >= off) ? sd[t - off] : 0;
        __syncthreads();
        sd[t] += v;
    }
    __syncthreads();
    int excl = sd[t] - s;
    if (base + 0 < n) scan[base + 0] = excl;
    if (base + 1 < n) scan[base + 1] = excl + d0;
    if (base + 2 < n) scan[base + 2] = excl + d0 + d1;
    if (base + 3 < n) scan[base + 3] = excl + d0 + d1 + d2;
    if (t == 255) part[blockIdx.x] = sd[255];
}

// ---------------- scan fixup: inline partial-scan + add-back -----------------
__global__ __launch_bounds__(256) void k_scan_add(const int* __restrict__ scan,
                                                  const int* __restrict__ part,
                                                  int* __restrict__ start,
                                                  int* __restrict__ cursor,
                                                  int n, int E, int nb) {
    __shared__ int sp[128];
    __shared__ int so[128];
    int t = threadIdx.x;
    if (t < 128) {
        int s = (t < nb) ? __ldg(part + t) : 0;
        sp[t] = s;
        so[t] = s;
    }
    __syncthreads();
#pragma unroll
    for (int off = 1; off < 128; off <<= 1) {
        int v = 0;
        if (t < 128 && t >= off) v = sp[t - off];
        __syncthreads();
        if (t < 128) sp[t] += v;
        __syncthreads();
    }
    int i = blockIdx.x * 256 + t;
    if (i < n) {
        int b = i >> 10;
        int v = scan[i] + sp[b] - so[b];     // + exclusive prefix of partials
        start[i] = v;
        cursor[i] = v;
    }
    if (i == 0) start[n] = E;
}

// ---------------- per-edge weight + direct CSR fill (float4 geometry) --------
__global__ __launch_bounds__(256) void k_edge_w(const int* __restrict__ edges,
                                                const float4* __restrict__ verts4,
                                                const float4* __restrict__ nacc4,
                                                const float* __restrict__ W1,
                                                const float* __restrict__ b1,
                                                const float* __restrict__ W2,
                                                const float* __restrict__ b2,
                                                int* __restrict__ cursor,
                                                int* __restrict__ csr_src,
                                                float* __restrict__ csr_w, int E) {
    __shared__ float sW1[96];
    __shared__ float sb1[32];
    __shared__ float sW2[192];
    __shared__ float sb2[6];
    int tid = threadIdx.x;
    for (int i = tid; i < 96;  i += blockDim.x) sW1[i] = W1[i];
    for (int i = tid; i < 32;  i += blockDim.x) sb1[i] = b1[i];
    for (int i = tid; i < 192; i += blockDim.x) sW2[i] = W2[i];
    for (int i = tid; i < 6;   i += blockDim.x) sb2[i] = b2[i];
    __syncthreads();

    int e = blockIdx.x * blockDim.x + tid;
    if (e >= E) return;
    int src = __ldg(edges + e);
    int dst = __ldg(edges + E + e);

    float4 vs = __ldg(verts4 + src);
    float4 vd = __ldg(verts4 + dst);
    float dx = vd.x - vs.x, dy = vd.y - vs.y, dz = vd.z - vs.z;
    float4 rn = __ldg(nacc4 + src);
    float len = sqrtf(rn.x * rn.x + rn.y * rn.y + rn.z * rn.z);
    float inv = 1.0f / (len + 1e-8f);
    float nx = rn.x * inv, ny = rn.y * inv, nz = rn.z * inv;

    float dot = dx * nx + dy * ny + dz * nz;
    float t0 = dx - dot * nx, t1 = dy - dot * ny, t2 = dz - dot * nz;

    float th[6];
#pragma unroll
    for (int m = 0; m < 6; m++) th[m] = sb2[m];
#pragma unroll
    for (int j = 0; j < 32; j++) {
        float h = sb1[j] + t0 * sW1[j] + t1 * sW1[32 + j] + t2 * sW1[64 + j];
        h = fmaxf(h, 0.0f);
#pragma unroll
        for (int m = 0; m < 6; m++) th[m] += h * sW2[j * 6 + m];
    }
    float s0 = th[0] * t0 + th[1] * t1 + th[2] * t2;
    float s1 = th[1] * t0 + th[3] * t1 + th[4] * t2;
    float s2 = th[2] * t0 + th[4] * t1 + th[5] * t2;
    float q = s0 * s0 + s1 * s1 + s2 * s2;
    float wv = expf(-q);

    int pos = atomicAdd(&cursor[dst], 1);
    csr_src[pos] = src;
    csr_w[pos] = wv;
}

// ---------------- gather + fused column stats --------------------------------
__global__ __launch_bounds__(256) void k_gather_stats(const int* __restrict__ start,
                                                      const int* __restrict__ csr_src,
                                                      const float* __restrict__ csr_w,
                                                      const float* __restrict__ x,
                                                      float* __restrict__ p,
                                                      float* __restrict__ stats, int n) {
    int warp = threadIdx.x >> 5, lane = threadIdx.x & 31;
    float4 s1 = make_float4(0.f, 0.f, 0.f, 0.f);
    float4 s2 = make_float4(0.f, 0.f, 0.f, 0.f);

    for (int it = 0; it < 8; it++) {
        int v = blockIdx.x * 64 + it * 8 + warp;
        if (v >= n) break;
        int beg = __ldg(start + v);
        int end = __ldg(start + v + 1);
        float4 acc = make_float4(0.f, 0.f, 0.f, 0.f);
        float dsum = 0.0f;
        int i = beg;
        for (; i + 4 <= end; i += 4) {
            int e0 = __ldg(csr_src + i + 0);
            int e1 = __ldg(csr_src + i + 1);
            int e2 = __ldg(csr_src + i + 2);
            int e3 = __ldg(csr_src + i + 3);
            float w0 = __ldg(csr_w + i + 0);
            float w1 = __ldg(csr_w + i + 1);
            float w2 = __ldg(csr_w + i + 2);
            float w3 = __ldg(csr_w + i + 3);
            float4 a = __ldg((const float4*)(x + (size_t)e0 * C) + lane);
            float4 b = __ldg((const float4*)(x + (size_t)e1 * C) + lane);
            float4 c = __ldg((const float4*)(x + (size_t)e2 * C) + lane);
            float4 d = __ldg((const float4*)(x + (size_t)e3 * C) + lane);
            dsum += (w0 + w1) + (w2 + w3);
            acc.x += w0 * a.x + w1 * b.x + w2 * c.x + w3 * d.x;
            acc.y += w0 * a.y + w1 * b.y + w2 * c.y + w3 * d.y;
            acc.z += w0 * a.z + w1 * b.z + w2 * c.z + w3 * d.z;
            acc.w += w0 * a.w + w1 * b.w + w2 * c.w + w3 * d.w;
        }
        for (; i < end; i++) {
            int s = __ldg(csr_src + i);
            float we = __ldg(csr_w + i);
            float4 xv = __ldg((const float4*)(x + (size_t)s * C) + lane);
            dsum += we;
            acc.x += we * xv.x; acc.y += we * xv.y; acc.z += we * xv.z; acc.w += we * xv.w;
        }
        float rd = 1.0f / (dsum + 1e-5f);
        acc.x *= rd; acc.y *= rd; acc.z *= rd; acc.w *= rd;
        *((float4*)(p + (size_t)v * C) + lane) = acc;
        s1.x += acc.x; s1.y += acc.y; s1.z += acc.z; s1.w += acc.w;
        s2.x += acc.x * acc.x; s2.y += acc.y * acc.y; s2.z += acc.z * acc.z; s2.w += acc.w * acc.w;
    }

    __shared__ float4 red[8][32];
    red[warp][lane] = s1;
    __syncthreads();
    if (threadIdx.x < 128) {
        int col = threadIdx.x;
        float s = 0.0f;
#pragma unroll
        for (int w = 0; w < 8; w++) {
            const float* r = (const float*)&red[w][col >> 2];
            s += r[col & 3];
        }
        atomicAdd(&stats[col], s);
    }
    __syncthreads();
    red[warp][lane] = s2;
    __syncthreads();
    if (threadIdx.x < 128) {
        int col = threadIdx.x;
        float s = 0.0f;
#pragma unroll
        for (int w = 0; w < 8; w++) {
            const float* r = (const float*)&red[w][col >> 2];
            s += r[col & 3];
        }
        atomicAdd(&stats[C + col], s);
    }
}

// ---------------- final: (inline mu/rstd) normalize + ELU, float4 ------------
__global__ __launch_bounds__(256) void k_final(const float* __restrict__ p,
                                               const float* __restrict__ stats,
                                               float* __restrict__ out, int n) {
    __shared__ float smu[C];
    __shared__ float srstd[C];
    int tid = threadIdx.x;
    if (tid < C) {
        float m = stats[tid] / (float)n;
        float var = (stats[C + tid] - (float)n * m * m) / (float)(n - 1);
        var = fmaxf(var, 0.0f);
        smu[tid] = m;
        srstd[tid] = 1.0f / (sqrtf(var) + 1e-5f);
    }
    __syncthreads();
    size_t i4 = (size_t)blockIdx.x * blockDim.x + tid;    // float4 index
    if (i4 >= (size_t)n * 32) return;
    int c4 = (int)(i4 & 31) * 4;
    float4 v = __ldg((const float4*)p + i4);
    float y0 = (v.x - smu[c4 + 0]) * srstd[c4 + 0];
    float y1 = (v.y - smu[c4 + 1]) * srstd[c4 + 1];
    float y2 = (v.z - smu[c4 + 2]) * srstd[c4 + 2];
    float y3 = (v.w - smu[c4 + 3]) * srstd[c4 + 3];
    float4 o;
    o.x = (y0 > 0.0f) ? y0 : expm1f(y0);
    o.y = (y1 > 0.0f) ? y1 : expm1f(y1);
    o.z = (y2 > 0.0f) ? y2 : expm1f(y2);
    o.w = (y3 > 0.0f) ? y3 : expm1f(y3);
    ((float4*)out)[i4] = o;
}

// ---------------- launch -----------------------------------------------------
extern "C" void kernel_launch(void* const* d_in, const int* in_sizes, int n_in,
                              void* d_out, int out_size) {
    const float* features = (const float*)d_in[0];
    const float* vertices = (const float*)d_in[1];
    const int*   edges    = (const int*)d_in[2];
    const int*   faces    = (const int*)d_in[3];
    const float* W1       = (const float*)d_in[4];
    const float* b1       = (const float*)d_in[5];
    const float* W2       = (const float*)d_in[6];
    const float* b2       = (const float*)d_in[7];
    const float* Wlin     = (const float*)d_in[8];
    const float* blin     = (const float*)d_in[9];

    int n = in_sizes[0] / C;
    int e = in_sizes[2] / 2;
    int f = in_sizes[3] / 3;
    if (n > NMAX) n = NMAX;
    if (e > EMAX) e = EMAX;
    if (f > FMAX) f = FMAX;

    float *p_x, *p_p, *p_stats, *p_csrw;
    float4 *p_nacc4, *p_verts4;
    int *p_deg, *p_scan, *p_part, *p_start, *p_cursor, *p_csrsrc;
    uint32_t *p_bh, *p_bl;
    cudaGetSymbolAddress((void**)&p_x, g_x);
    cudaGetSymbolAddress((void**)&p_p, g_p);
    cudaGetSymbolAddress((void**)&p_nacc4, g_nacc4);
    cudaGetSymbolAddress((void**)&p_verts4, g_verts4);
    cudaGetSymbolAddress((void**)&p_stats, g_stats);
    cudaGetSymbolAddress((void**)&p_deg, g_deg);
    cudaGetSymbolAddress((void**)&p_scan, g_scan);
    cudaGetSymbolAddress((void**)&p_part, g_part);
    cudaGetSymbolAddress((void**)&p_start, g_start);
    cudaGetSymbolAddress((void**)&p_cursor, g_cursor);
    cudaGetSymbolAddress((void**)&p_csrsrc, g_csr_src);
    cudaGetSymbolAddress((void**)&p_csrw, g_csr_w);
    cudaGetSymbolAddress((void**)&p_bh, g_Bh);
    cudaGetSymbolAddress((void**)&p_bl, g_Bl);

    float* out = (float*)d_out;

    const int GEMM_SMEM = 2 * 64 * BPITCH * 4;    // 36864 bytes
    cudaFuncSetAttribute(k_gemm_face, cudaFuncAttributeMaxDynamicSharedMemorySize, GEMM_SMEM);

    int mainBlocks = (n + 255) / 256;
    int gemmBlocks = ((n + 127) / 128) * 2;
    int faceBlocks = (f + e + 255) / 256;
    int nb = (n + 1023) / 1024;                   // scan blocks (<=128)

    k_init<<<mainBlocks + 32, 256>>>(vertices, p_verts4, p_nacc4, p_deg, p_stats,
                                     Wlin, p_bh, p_bl, n, mainBlocks);             // 0
    k_gemm_face<<<gemmBlocks + faceBlocks, 256, GEMM_SMEM>>>(
        features, p_bh, p_bl, blin, p_x,
        faces, p_verts4, edges, p_nacc4, p_deg,
        n, f, e, gemmBlocks);                                                      // 1
    k_scan_block<<<nb, 256>>>(p_deg, p_scan, p_part, n);                           // 2
    k_scan_add<<<(n + 255) / 256, 256>>>(p_scan, p_part, p_start, p_cursor,
                                         n, e, nb);                                // 3
    k_edge_w<<<(e + 255) / 256, 256>>>(edges, p_verts4, p_nacc4, W1, b1, W2, b2,
                                       p_cursor, p_csrsrc, p_csrw, e);             // 4 (ncu)
    k_gather_stats<<<(n + 63) / 64, 256>>>(p_start, p_csrsrc, p_csrw, p_x, p_p,
                                           p_stats, n);                            // 5
    k_final<<<(n * 32 + 255) / 256, 256>>>(p_p, p_stats, out, n);                  // 6
}

// round 17
// speedup vs baseline: 1.6492x; 1.0288x over previous
#include <cuda_runtime.h>
#include <cuda_bf16.h>
#include <cstdint>
#include <cstddef>

#define NMAX 100000
#define EMAX 600000
#define FMAX 200000
#define C    128

// ---------------- scratch (static device globals; no runtime alloc) ----------
__device__ float g_x[(size_t)NMAX * C];      // features @ Wlin + blin
__device__ float g_p[(size_t)NMAX * C];      // aggregated & den-normalized rows
__device__ float4 g_nacc4[NMAX];             // accumulated face normals (xyz, pad)
__device__ float4 g_verts4[NMAX];            // repacked vertices (xyz, 0)
__device__ float g_stats[256];               // colsum[128], colsum2[128]
// CSR-by-dst
__device__ int   g_deg[NMAX];
__device__ int   g_scan[NMAX];               // in-block exclusive scan
__device__ int   g_part[128];                // block partial sums
__device__ int   g_start[NMAX + 1];
__device__ int   g_cursor[NMAX];
__device__ int   g_csr_src[EMAX];
__device__ float g_csr_w[EMAX];
// pre-converted W bf16 hi/lo, layout [n][paired-k] pitch 72 u32 (LDS.64 pairs)
#define BPITCH 72
__device__ uint32_t g_Bh[128 * BPITCH];
__device__ uint32_t g_Bl[128 * BPITCH];

// ---------------- init: zero + vertex repack + prep B (fused) ----------------
__global__ void k_init(const float* __restrict__ verts, float4* __restrict__ verts4,
                       float4* __restrict__ nacc4, int* __restrict__ deg,
                       float* __restrict__ stats,
                       const float* __restrict__ W,
                       uint32_t* __restrict__ bh, uint32_t* __restrict__ bl,
                       int n, int mainBlocks) {
    if ((int)blockIdx.x < mainBlocks) {
        int i = blockIdx.x * 256 + threadIdx.x;
        if (i < n) {
            verts4[i] = make_float4(__ldg(verts + 3 * i), __ldg(verts + 3 * i + 1),
                                    __ldg(verts + 3 * i + 2), 0.0f);
            nacc4[i] = make_float4(0.f, 0.f, 0.f, 0.f);
            deg[i] = 0;
        }
        if (i < 256) stats[i] = 0.0f;
    } else {
        int idx = (blockIdx.x - mainBlocks) * 256 + threadIdx.x;   // 128*64
        if (idx >= 128 * 64) return;
        int c = idx >> 6, kp = idx & 63;
        float v0 = __ldg(W + (size_t)(2 * kp) * C + c);
        float v1 = __ldg(W + (size_t)(2 * kp + 1) * C + c);
        __nv_bfloat16 h0 = __float2bfloat16_rn(v0);
        __nv_bfloat16 h1 = __float2bfloat16_rn(v1);
        __nv_bfloat16 l0 = __float2bfloat16_rn(v0 - __bfloat162float(h0));
        __nv_bfloat16 l1 = __float2bfloat16_rn(v1 - __bfloat162float(h1));
        __nv_bfloat162 H(h0, h1), L(l0, l1);
        int off = (kp >> 3) * 8 + (kp & 3) * 2 + ((kp >> 2) & 1);
        bh[c * BPITCH + off] = *(uint32_t*)&H;
        bl[c * BPITCH + off] = *(uint32_t*)&L;
    }
}

// ---------------- mma.sync helpers -------------------------------------------
__device__ __forceinline__ void mma16816(float* c, const uint32_t* a,
                                         uint32_t b0, uint32_t b1) {
    asm volatile(
        "mma.sync.aligned.m16n8k16.row.col.f32.bf16.bf16.f32 "
        "{%0,%1,%2,%3}, {%4,%5,%6,%7}, {%8,%9}, {%0,%1,%2,%3};"
        : "+f"(c[0]), "+f"(c[1]), "+f"(c[2]), "+f"(c[3])
        : "r"(a[0]), "r"(a[1]), "r"(a[2]), "r"(a[3]), "r"(b0), "r"(b1));
}

__device__ __forceinline__ void cvt2(float2 v, uint32_t& hi, uint32_t& lo) {
    __nv_bfloat16 h0 = __float2bfloat16_rn(v.x);
    __nv_bfloat16 h1 = __float2bfloat16_rn(v.y);
    __nv_bfloat16 l0 = __float2bfloat16_rn(v.x - __bfloat162float(h0));
    __nv_bfloat16 l1 = __float2bfloat16_rn(v.y - __bfloat162float(h1));
    __nv_bfloat162 H(h0, h1), L(l0, l1);
    hi = *(uint32_t*)&H;
    lo = *(uint32_t*)&L;
}

__device__ __forceinline__ void red_add_v4(float4* p, float x, float y, float z) {
    asm volatile("red.global.add.v4.f32 [%0], {%1, %2, %3, %4};"
                 :: "l"(p), "f"(x), "f"(y), "f"(z), "f"(0.0f) : "memory");
}

// ---------------- face normals (v4 RED) + dst degree count (stream 2) --------
__global__ void k_face_count(const int* __restrict__ faces,
                             const float4* __restrict__ verts4,
                             const int* __restrict__ edges,
                             float4* __restrict__ nacc4,
                             int* __restrict__ deg, int F, int E) {
    int t = blockIdx.x * blockDim.x + threadIdx.x;
    if (t < F) {
        int f = t;
        int i0 = __ldg(faces + f);
        int i1 = __ldg(faces + F + f);
        int i2 = __ldg(faces + 2 * F + f);
        float4 v0 = __ldg(verts4 + i0);
        float4 v1 = __ldg(verts4 + i1);
        float4 v2 = __ldg(verts4 + i2);
        float ax = v1.x - v0.x, ay = v1.y - v0.y, az = v1.z - v0.z;
        float bx = v2.x - v0.x, by = v2.y - v0.y, bz = v2.z - v0.z;
        float nx = ay * bz - az * by;
        float ny = az * bx - ax * bz;
        float nz = ax * by - ay * bx;
        red_add_v4(nacc4 + i0, nx, ny, nz);
        red_add_v4(nacc4 + i1, nx, ny, nz);
        red_add_v4(nacc4 + i2, nx, ny, nz);
    } else {
        int e = t - F;
        if (e < E) atomicAdd(&deg[__ldg(edges + E + e)], 1);
    }
}

// ---------------- bf16x3 mma GEMM (default stream) ---------------------------
extern __shared__ uint32_t sB[];   // [2][64*BPITCH] hi then lo

__global__ __launch_bounds__(256, 3) void k_gemm(
    const float* __restrict__ feat, const uint32_t* __restrict__ gBh,
    const uint32_t* __restrict__ gBl, const float* __restrict__ bias,
    float* __restrict__ xout, int n) {
    const int BSZ = 64 * BPITCH;           // 4608 u32 = 18432 B per matrix
    int tid = threadIdx.x;
    int bx = blockIdx.x >> 1;
    int nh = blockIdx.x & 1;               // n-half
    {
        const float4* s1 = (const float4*)(gBh + nh * BSZ);
        const float4* s2 = (const float4*)(gBl + nh * BSZ);
        float4* d1 = (float4*)sB;
        float4* d2 = (float4*)(sB + BSZ);
        for (int i = tid; i < BSZ / 4; i += 256) { d1[i] = __ldg(s1 + i); d2[i] = __ldg(s2 + i); }
    }
    __syncthreads();

    int warp = tid >> 5, lane = tid & 31;
    int gid = lane >> 2, tg = lane & 3;
    int r0 = bx * 128 + warp * 16 + gid;
    int r1 = r0 + 8;
    int r0c = (r0 < n) ? r0 : (n - 1);
    int r1c = (r1 < n) ? r1 : (n - 1);
    const float* A0 = feat + (size_t)r0c * C;
    const float* A1 = feat + (size_t)r1c * C;

    float acc[8][4];
#pragma unroll
    for (int t = 0; t < 8; t++) { acc[t][0] = acc[t][1] = acc[t][2] = acc[t][3] = 0.0f; }

    const uint32_t* Bh = sB;
    const uint32_t* Bl = sB + BSZ;

#pragma unroll
    for (int ch = 0; ch < 8; ch++) {
        int k0 = ch * 16 + tg * 2;
        float2 p00 = __ldg((const float2*)(A0 + k0));
        float2 p10 = __ldg((const float2*)(A1 + k0));
        float2 p01 = __ldg((const float2*)(A0 + k0 + 8));
        float2 p11 = __ldg((const float2*)(A1 + k0 + 8));
        uint32_t ah[4], al[4];
        cvt2(p00, ah[0], al[0]);
        cvt2(p10, ah[1], al[1]);
        cvt2(p01, ah[2], al[2]);
        cvt2(p11, ah[3], al[3]);
        int bbase = ch * 8 + tg * 2;
#pragma unroll
        for (int t = 0; t < 8; t++) {
            int ci = (t * 8 + gid) * BPITCH + bbase;
            uint2 bh2 = *(const uint2*)(Bh + ci);
            uint2 bl2 = *(const uint2*)(Bl + ci);
            mma16816(acc[t], ah, bh2.x, bh2.y);
            mma16816(acc[t], ah, bl2.x, bl2.y);
            mma16816(acc[t], al, bh2.x, bh2.y);
        }
    }

#pragma unroll
    for (int t = 0; t < 8; t++) {
        int c0 = nh * 64 + t * 8 + tg * 2;
        float2 bv = __ldg((const float2*)(bias + c0));
        if (r0 < n) {
            float2 o = make_float2(acc[t][0] + bv.x, acc[t][1] + bv.y);
            *(float2*)(xout + (size_t)r0 * C + c0) = o;
        }
        if (r1 < n) {
            float2 o = make_float2(acc[t][2] + bv.x, acc[t][3] + bv.y);
            *(float2*)(xout + (size_t)r1 * C + c0) = o;
        }
    }
}

// ---------------- exclusive scan over deg: block pass ------------------------
__global__ __launch_bounds__(256) void k_scan_block(const int* __restrict__ deg,
                                                    int* __restrict__ scan,
                                                    int* __restrict__ part, int n) {
    __shared__ int sd[256];
    int t = threadIdx.x;
    int base = blockIdx.x * 1024 + t * 4;
    int d0 = (base + 0 < n) ? deg[base + 0] : 0;
    int d1 = (base + 1 < n) ? deg[base + 1] : 0;
    int d2 = (base + 2 < n) ? deg[base + 2] : 0;
    int d3 = (base + 3 < n) ? deg[base + 3] : 0;
    int s = d0 + d1 + d2 + d3;
    sd[t] = s;
#pragma unroll
    for (int off = 1; off < 256; off <<= 1) {
        __syncthreads();
        int v = (t >= off) ? sd[t - off] : 0;
        __syncthreads();
        sd[t] += v;
    }
    __syncthreads();
    int excl = sd[t] - s;
    if (base + 0 < n) scan[base + 0] = excl;
    if (base + 1 < n) scan[base + 1] = excl + d0;
    if (base + 2 < n) scan[base + 2] = excl + d0 + d1;
    if (base + 3 < n) scan[base + 3] = excl + d0 + d1 + d2;
    if (t == 255) part[blockIdx.x] = sd[255];
}

// ---------------- scan fixup: inline partial-scan + add-back -----------------
__global__ __launch_bounds__(256) void k_scan_add(const int* __restrict__ scan,
                                                  const int* __restrict__ part,
                                                  int* __restrict__ start,
                                                  int* __restrict__ cursor,
                                                  int n, int E, int nb) {
    __shared__ int sp[128];
    __shared__ int so[128];
    int t = threadIdx.x;
    if (t < 128) {
        int s = (t < nb) ? __ldg(part + t) : 0;
        sp[t] = s;
        so[t] = s;
    }
    __syncthreads();
#pragma unroll
    for (int off = 1; off < 128; off <<= 1) {
        int v = 0;
        if (t < 128 && t >= off) v = sp[t - off];
        __syncthreads();
        if (t < 128) sp[t] += v;
        __syncthreads();
    }
    int i = blockIdx.x * 256 + t;
    if (i < n) {
        int b = i >> 10;
        int v = scan[i] + sp[b] - so[b];     // + exclusive prefix of partials
        start[i] = v;
        cursor[i] = v;
    }
    if (i == 0) start[n] = E;
}

// ---------------- per-edge weight + direct CSR fill (float4 geometry) --------
__global__ __launch_bounds__(256) void k_edge_w(const int* __restrict__ edges,
                                                const float4* __restrict__ verts4,
                                                const float4* __restrict__ nacc4,
                                                const float* __restrict__ W1,
                                                const float* __restrict__ b1,
                                                const float* __restrict__ W2,
                                                const float* __restrict__ b2,
                                                int* __restrict__ cursor,
                                                int* __restrict__ csr_src,
                                                float* __restrict__ csr_w, int E) {
    __shared__ float sW1[96];
    __shared__ float sb1[32];
    __shared__ float sW2[192];
    __shared__ float sb2[6];
    int tid = threadIdx.x;
    for (int i = tid; i < 96;  i += blockDim.x) sW1[i] = W1[i];
    for (int i = tid; i < 32;  i += blockDim.x) sb1[i] = b1[i];
    for (int i = tid; i < 192; i += blockDim.x) sW2[i] = W2[i];
    for (int i = tid; i < 6;   i += blockDim.x) sb2[i] = b2[i];
    __syncthreads();

    int e = blockIdx.x * blockDim.x + tid;
    if (e >= E) return;
    int src = __ldg(edges + e);
    int dst = __ldg(edges + E + e);

    float4 vs = __ldg(verts4 + src);
    float4 vd = __ldg(verts4 + dst);
    float dx = vd.x - vs.x, dy = vd.y - vs.y, dz = vd.z - vs.z;
    float4 rn = __ldg(nacc4 + src);
    float len = sqrtf(rn.x * rn.x + rn.y * rn.y + rn.z * rn.z);
    float inv = 1.0f / (len + 1e-8f);
    float nx = rn.x * inv, ny = rn.y * inv, nz = rn.z * inv;

    float dot = dx * nx + dy * ny + dz * nz;
    float t0 = dx - dot * nx, t1 = dy - dot * ny, t2 = dz - dot * nz;

    float th[6];
#pragma unroll
    for (int m = 0; m < 6; m++) th[m] = sb2[m];
#pragma unroll
    for (int j = 0; j < 32; j++) {
        float h = sb1[j] + t0 * sW1[j] + t1 * sW1[32 + j] + t2 * sW1[64 + j];
        h = fmaxf(h, 0.0f);
#pragma unroll
        for (int m = 0; m < 6; m++) th[m] += h * sW2[j * 6 + m];
    }
    float s0 = th[0] * t0 + th[1] * t1 + th[2] * t2;
    float s1 = th[1] * t0 + th[3] * t1 + th[4] * t2;
    float s2 = th[2] * t0 + th[4] * t1 + th[5] * t2;
    float q = s0 * s0 + s1 * s1 + s2 * s2;
    float wv = expf(-q);

    int pos = atomicAdd(&cursor[dst], 1);
    csr_src[pos] = src;
    csr_w[pos] = wv;
}

// ---------------- gather + fused column stats --------------------------------
__global__ __launch_bounds__(256) void k_gather_stats(const int* __restrict__ start,
                                                      const int* __restrict__ csr_src,
                                                      const float* __restrict__ csr_w,
                                                      const float* __restrict__ x,
                                                      float* __restrict__ p,
                                                      float* __restrict__ stats, int n) {
    int warp = threadIdx.x >> 5, lane = threadIdx.x & 31;
    float4 s1 = make_float4(0.f, 0.f, 0.f, 0.f);
    float4 s2 = make_float4(0.f, 0.f, 0.f, 0.f);

    for (int it = 0; it < 8; it++) {
        int v = blockIdx.x * 64 + it * 8 + warp;
        if (v >= n) break;
        int beg = __ldg(start + v);
        int end = __ldg(start + v + 1);
        float4 acc = make_float4(0.f, 0.f, 0.f, 0.f);
        float dsum = 0.0f;
        int i = beg;
        for (; i + 4 <= end; i += 4) {
            int e0 = __ldg(csr_src + i + 0);
            int e1 = __ldg(csr_src + i + 1);
            int e2 = __ldg(csr_src + i + 2);
            int e3 = __ldg(csr_src + i + 3);
            float w0 = __ldg(csr_w + i + 0);
            float w1 = __ldg(csr_w + i + 1);
            float w2 = __ldg(csr_w + i + 2);
            float w3 = __ldg(csr_w + i + 3);
            float4 a = __ldg((const float4*)(x + (size_t)e0 * C) + lane);
            float4 b = __ldg((const float4*)(x + (size_t)e1 * C) + lane);
            float4 c = __ldg((const float4*)(x + (size_t)e2 * C) + lane);
            float4 d = __ldg((const float4*)(x + (size_t)e3 * C) + lane);
            dsum += (w0 + w1) + (w2 + w3);
            acc.x += w0 * a.x + w1 * b.x + w2 * c.x + w3 * d.x;
            acc.y += w0 * a.y + w1 * b.y + w2 * c.y + w3 * d.y;
            acc.z += w0 * a.z + w1 * b.z + w2 * c.z + w3 * d.z;
            acc.w += w0 * a.w + w1 * b.w + w2 * c.w + w3 * d.w;
        }
        for (; i < end; i++) {
            int s = __ldg(csr_src + i);
            float we = __ldg(csr_w + i);
            float4 xv = __ldg((const float4*)(x + (size_t)s * C) + lane);
            dsum += we;
            acc.x += we * xv.x; acc.y += we * xv.y; acc.z += we * xv.z; acc.w += we * xv.w;
        }
        float rd = 1.0f / (dsum + 1e-5f);
        acc.x *= rd; acc.y *= rd; acc.z *= rd; acc.w *= rd;
        *((float4*)(p + (size_t)v * C) + lane) = acc;
        s1.x += acc.x; s1.y += acc.y; s1.z += acc.z; s1.w += acc.w;
        s2.x += acc.x * acc.x; s2.y += acc.y * acc.y; s2.z += acc.z * acc.z; s2.w += acc.w * acc.w;
    }

    __shared__ float4 red[8][32];
    red[warp][lane] = s1;
    __syncthreads();
    if (threadIdx.x < 128) {
        int col = threadIdx.x;
        float s = 0.0f;
#pragma unroll
        for (int w = 0; w < 8; w++) {
            const float* r = (const float*)&red[w][col >> 2];
            s += r[col & 3];
        }
        atomicAdd(&stats[col], s);
    }
    __syncthreads();
    red[warp][lane] = s2;
    __syncthreads();
    if (threadIdx.x < 128) {
        int col = threadIdx.x;
        float s = 0.0f;
#pragma unroll
        for (int w = 0; w < 8; w++) {
            const float* r = (const float*)&red[w][col >> 2];
            s += r[col & 3];
        }
        atomicAdd(&stats[C + col], s);
    }
}

// ---------------- final: (inline mu/rstd) normalize + ELU, float4 ------------
__global__ __launch_bounds__(256) void k_final(const float* __restrict__ p,
                                               const float* __restrict__ stats,
                                               float* __restrict__ out, int n) {
    __shared__ float smu[C];
    __shared__ float srstd[C];
    int tid = threadIdx.x;
    if (tid < C) {
        float m = stats[tid] / (float)n;
        float var = (stats[C + tid] - (float)n * m * m) / (float)(n - 1);
        var = fmaxf(var, 0.0f);
        smu[tid] = m;
        srstd[tid] = 1.0f / (sqrtf(var) + 1e-5f);
    }
    __syncthreads();
    size_t i4 = (size_t)blockIdx.x * blockDim.x + tid;    // float4 index
    if (i4 >= (size_t)n * 32) return;
    int c4 = (int)(i4 & 31) * 4;
    float4 v = __ldg((const float4*)p + i4);
    float y0 = (v.x - smu[c4 + 0]) * srstd[c4 + 0];
    float y1 = (v.y - smu[c4 + 1]) * srstd[c4 + 1];
    float y2 = (v.z - smu[c4 + 2]) * srstd[c4 + 2];
    float y3 = (v.w - smu[c4 + 3]) * srstd[c4 + 3];
    float4 o;
    o.x = (y0 > 0.0f) ? y0 : expm1f(y0);
    o.y = (y1 > 0.0f) ? y1 : expm1f(y1);
    o.z = (y2 > 0.0f) ? y2 : expm1f(y2);
    o.w = (y3 > 0.0f) ? y3 : expm1f(y3);
    ((float4*)out)[i4] = o;
}

// ---------------- launch -----------------------------------------------------
extern "C" void kernel_launch(void* const* d_in, const int* in_sizes, int n_in,
                              void* d_out, int out_size) {
    const float* features = (const float*)d_in[0];
    const float* vertices = (const float*)d_in[1];
    const int*   edges    = (const int*)d_in[2];
    const int*   faces    = (const int*)d_in[3];
    const float* W1       = (const float*)d_in[4];
    const float* b1       = (const float*)d_in[5];
    const float* W2       = (const float*)d_in[6];
    const float* b2       = (const float*)d_in[7];
    const float* Wlin     = (const float*)d_in[8];
    const float* blin     = (const float*)d_in[9];

    int n = in_sizes[0] / C;
    int e = in_sizes[2] / 2;
    int f = in_sizes[3] / 3;
    if (n > NMAX) n = NMAX;
    if (e > EMAX) e = EMAX;
    if (f > FMAX) f = FMAX;

    float *p_x, *p_p, *p_stats, *p_csrw;
    float4 *p_nacc4, *p_verts4;
    int *p_deg, *p_scan, *p_part, *p_start, *p_cursor, *p_csrsrc;
    uint32_t *p_bh, *p_bl;
    cudaGetSymbolAddress((void**)&p_x, g_x);
    cudaGetSymbolAddress((void**)&p_p, g_p);
    cudaGetSymbolAddress((void**)&p_nacc4, g_nacc4);
    cudaGetSymbolAddress((void**)&p_verts4, g_verts4);
    cudaGetSymbolAddress((void**)&p_stats, g_stats);
    cudaGetSymbolAddress((void**)&p_deg, g_deg);
    cudaGetSymbolAddress((void**)&p_scan, g_scan);
    cudaGetSymbolAddress((void**)&p_part, g_part);
    cudaGetSymbolAddress((void**)&p_start, g_start);
    cudaGetSymbolAddress((void**)&p_cursor, g_cursor);
    cudaGetSymbolAddress((void**)&p_csrsrc, g_csr_src);
    cudaGetSymbolAddress((void**)&p_csrw, g_csr_w);
    cudaGetSymbolAddress((void**)&p_bh, g_Bh);
    cudaGetSymbolAddress((void**)&p_bl, g_Bl);

    float* out = (float*)d_out;

    // one-time side stream + fork/join events (host resources only; created on
    // the first, uncaptured correctness call and reused under graph capture)
    static cudaStream_t s2 = nullptr;
    static cudaEvent_t ev_fork = nullptr, ev_join = nullptr;
    if (s2 == nullptr) {
        cudaStreamCreateWithFlags(&s2, cudaStreamNonBlocking);
        cudaEventCreateWithFlags(&ev_fork, cudaEventDisableTiming);
        cudaEventCreateWithFlags(&ev_join, cudaEventDisableTiming);
    }

    const int GEMM_SMEM = 2 * 64 * BPITCH * 4;    // 36864 bytes
    cudaFuncSetAttribute(k_gemm, cudaFuncAttributeMaxDynamicSharedMemorySize, GEMM_SMEM);

    int mainBlocks = (n + 255) / 256;
    int gemmBlocks = ((n + 127) / 128) * 2;
    int nb = (n + 1023) / 1024;                   // scan blocks (<=128)

    // main stream: init, then fork
    k_init<<<mainBlocks + 32, 256>>>(vertices, p_verts4, p_nacc4, p_deg, p_stats,
                                     Wlin, p_bh, p_bl, n, mainBlocks);
    cudaEventRecord(ev_fork, 0);
    cudaStreamWaitEvent(s2, ev_fork, 0);

    // side stream: geometry -> scan -> edge weights (independent of GEMM)
    k_face_count<<<(f + e + 255) / 256, 256, 0, s2>>>(faces, p_verts4, edges,
                                                      p_nacc4, p_deg, f, e);
    k_scan_block<<<nb, 256, 0, s2>>>(p_deg, p_scan, p_part, n);
    k_scan_add<<<(n + 255) / 256, 256, 0, s2>>>(p_scan, p_part, p_start, p_cursor,
                                                n, e, nb);
    k_edge_w<<<(e + 255) / 256, 256, 0, s2>>>(edges, p_verts4, p_nacc4,
                                              W1, b1, W2, b2,
                                              p_cursor, p_csrsrc, p_csrw, e);
    cudaEventRecord(ev_join, s2);

    // main stream: GEMM runs concurrently with the side chain
    k_gemm<<<gemmBlocks, 256, GEMM_SMEM>>>(features, p_bh, p_bl, blin, p_x, n);

    // join, then aggregation + stats + final
    cudaStreamWaitEvent(0, ev_join, 0);
    k_gather_stats<<<(n + 63) / 64, 256>>>(p_start, p_csrsrc, p_csrw, p_x, p_p,
                                           p_stats, n);
    k_final<<<(n * 32 + 255) / 256, 256>>>(p_p, p_stats, out, n);
}